// round 1
// baseline (speedup 1.0000x reference)
#include <cuda_runtime.h>

#define DM 1024     // d_model
#define NH 16       // heads
#define DH 64       // head dim
#define BB 4        // batch
#define SS 1024     // seq
#define MT (BB*SS)  // 4096 rows total

// ---------------- scratch (device globals; no allocation allowed) ----------------
__device__ float g_gq[MT*DM];
__device__ float g_gk[MT*DM];
__device__ float g_gv[MT*DM];
__device__ float g_pq[MT*DM];
__device__ float g_pk[MT*DM];
__device__ float g_pv[MT*DM];
__device__ float g_att2[MT*DM];
__device__ float g_ctx[MT*DM];

// ---------------- GEMM: C[M,1024] = A[M,1024] @ W[1024,1024]^T + bias ----------
// 128x128 block tile, 8x8 per thread, BK=8, 256 threads.
__global__ __launch_bounds__(256) void gemm_bias_kernel(
    const float* __restrict__ A, const float* __restrict__ W,
    const float* __restrict__ bias, float* __restrict__ C)
{
    __shared__ float As[8][128];
    __shared__ float Ws[8][128];
    const int bm = blockIdx.y << 7;
    const int bn = blockIdx.x << 7;
    const int tid = threadIdx.x;
    const int tr = tid >> 4;         // 0..15
    const int tc = tid & 15;         // 0..15
    const int lr = tid >> 1;         // 0..127
    const int lc = (tid & 1) << 2;   // 0 or 4

    const float* Ap = A + (size_t)(bm + lr) * DM + lc;
    const float* Wp = W + (size_t)(bn + lr) * DM + lc;

    float acc[8][8];
#pragma unroll
    for (int i = 0; i < 8; i++)
#pragma unroll
        for (int j = 0; j < 8; j++) acc[i][j] = 0.f;

    for (int k0 = 0; k0 < DM; k0 += 8) {
        float4 av = *(const float4*)(Ap + k0);
        float4 wv = *(const float4*)(Wp + k0);
        As[lc+0][lr] = av.x; As[lc+1][lr] = av.y; As[lc+2][lr] = av.z; As[lc+3][lr] = av.w;
        Ws[lc+0][lr] = wv.x; Ws[lc+1][lr] = wv.y; Ws[lc+2][lr] = wv.z; Ws[lc+3][lr] = wv.w;
        __syncthreads();
#pragma unroll
        for (int kk = 0; kk < 8; kk++) {
            float a[8], b[8];
            *(float4*)&a[0] = *(const float4*)&As[kk][tr*8];
            *(float4*)&a[4] = *(const float4*)&As[kk][tr*8+4];
            *(float4*)&b[0] = *(const float4*)&Ws[kk][tc*8];
            *(float4*)&b[4] = *(const float4*)&Ws[kk][tc*8+4];
#pragma unroll
            for (int i = 0; i < 8; i++)
#pragma unroll
                for (int j = 0; j < 8; j++)
                    acc[i][j] = fmaf(a[i], b[j], acc[i][j]);
        }
        __syncthreads();
    }

    float4 b0 = *(const float4*)&bias[bn + tc*8];
    float4 b1 = *(const float4*)&bias[bn + tc*8 + 4];
#pragma unroll
    for (int i = 0; i < 8; i++) {
        float* Cp = C + (size_t)(bm + tr*8 + i) * DM + bn + tc*8;
        float4 r0 = make_float4(acc[i][0]+b0.x, acc[i][1]+b0.y, acc[i][2]+b0.z, acc[i][3]+b0.w);
        float4 r1 = make_float4(acc[i][4]+b1.x, acc[i][5]+b1.y, acc[i][6]+b1.z, acc[i][7]+b1.w);
        *(float4*)Cp     = r0;
        *(float4*)(Cp+4) = r1;
    }
}

// ---------------- Flash attention (fp32) ---------------------------------------
// O = softmax(Q K^T / 8) @ (V + Vadd), per (b,h). 64 queries x 64 keys tiles.
// Layouts in smem: Qs,Ks d-major [64][64]; Vs k-major [64][64]; Ps i-major.
// Thread (tr,tc) owns rows tr*4..+3, cols tc*4..+3 of each 64x64 tile.
__global__ __launch_bounds__(256) void attn_kernel(
    const float* __restrict__ Q, const float* __restrict__ Kp,
    const float* __restrict__ V, const float* __restrict__ Vadd,
    float* __restrict__ O)
{
    extern __shared__ float sm[];
    float* Qs = sm;            // 4096 floats
    float* Ks = sm + 4096;
    float* Vs = sm + 8192;
    float* Ps = sm + 12288;

    const int tid = threadIdx.x;
    const int tr = tid >> 4;
    const int tc = tid & 15;
    const int q0 = blockIdx.x << 6;      // query tile start
    const int bh = blockIdx.y;           // 0..63
    const int b  = bh >> 4;
    const int h  = bh & 15;
    const size_t base = ((size_t)b * SS) * DM + (size_t)h * DH;
    const float scale = 0.125f;

    // load Q tile transposed (d-major)
    for (int t = tid; t < 1024; t += 256) {
        int row = t >> 4;
        int d4  = (t & 15) << 2;
        float4 v = *(const float4*)(Q + base + (size_t)(q0 + row) * DM + d4);
        Qs[(d4+0)*64+row] = v.x; Qs[(d4+1)*64+row] = v.y;
        Qs[(d4+2)*64+row] = v.z; Qs[(d4+3)*64+row] = v.w;
    }

    float m[4], l[4], o[4][4];
#pragma unroll
    for (int r = 0; r < 4; r++) {
        m[r] = -1e30f; l[r] = 0.f;
#pragma unroll
        for (int c = 0; c < 4; c++) o[r][c] = 0.f;
    }
    __syncthreads();

    for (int kt = 0; kt < 16; kt++) {
        const int k0 = kt << 6;
        // load K (transposed) and V (+Vadd, k-major)
        for (int t = tid; t < 1024; t += 256) {
            int row = t >> 4;
            int d4  = (t & 15) << 2;
            size_t gi = base + (size_t)(k0 + row) * DM + d4;
            float4 kv = *(const float4*)(Kp + gi);
            Ks[(d4+0)*64+row] = kv.x; Ks[(d4+1)*64+row] = kv.y;
            Ks[(d4+2)*64+row] = kv.z; Ks[(d4+3)*64+row] = kv.w;
            float4 vv = *(const float4*)(V + gi);
            if (Vadd) {
                float4 va = *(const float4*)(Vadd + gi);
                vv.x += va.x; vv.y += va.y; vv.z += va.z; vv.w += va.w;
            }
            *(float4*)&Vs[row*64 + d4] = vv;
        }
        __syncthreads();

        // S = Q K^T  (4x4 per thread)
        float s[4][4];
#pragma unroll
        for (int r = 0; r < 4; r++)
#pragma unroll
            for (int c = 0; c < 4; c++) s[r][c] = 0.f;
#pragma unroll 4
        for (int d = 0; d < 64; d++) {
            float qa[4], kb[4];
            *(float4*)qa = *(const float4*)&Qs[d*64 + tr*4];
            *(float4*)kb = *(const float4*)&Ks[d*64 + tc*4];
#pragma unroll
            for (int r = 0; r < 4; r++)
#pragma unroll
                for (int c = 0; c < 4; c++)
                    s[r][c] = fmaf(qa[r], kb[c], s[r][c]);
        }

        // online softmax (row stats via 16-lane shuffles; lanes of a row group
        // sit in the same half-warp, so xor offsets 1..8 stay in-group)
#pragma unroll
        for (int r = 0; r < 4; r++) {
            float st[4];
#pragma unroll
            for (int c = 0; c < 4; c++) st[c] = s[r][c] * scale;
            float mt = fmaxf(fmaxf(st[0], st[1]), fmaxf(st[2], st[3]));
#pragma unroll
            for (int off = 8; off > 0; off >>= 1)
                mt = fmaxf(mt, __shfl_xor_sync(0xffffffffu, mt, off));
            float mn = fmaxf(m[r], mt);
            float al = __expf(m[r] - mn);
            float p[4], rs = 0.f;
#pragma unroll
            for (int c = 0; c < 4; c++) { p[c] = __expf(st[c] - mn); rs += p[c]; }
#pragma unroll
            for (int off = 8; off > 0; off >>= 1)
                rs += __shfl_xor_sync(0xffffffffu, rs, off);
            l[r] = l[r] * al + rs;
            m[r] = mn;
#pragma unroll
            for (int c = 0; c < 4; c++) o[r][c] *= al;
            *(float4*)&Ps[(tr*4+r)*64 + tc*4] = make_float4(p[0], p[1], p[2], p[3]);
        }
        __syncthreads();

        // O += P @ V
        for (int k4 = 0; k4 < 64; k4 += 4) {
            float pr[4][4];
#pragma unroll
            for (int r = 0; r < 4; r++)
                *(float4*)pr[r] = *(const float4*)&Ps[(tr*4+r)*64 + k4];
#pragma unroll
            for (int kk = 0; kk < 4; kk++) {
                float vb[4];
                *(float4*)vb = *(const float4*)&Vs[(k4+kk)*64 + tc*4];
#pragma unroll
                for (int r = 0; r < 4; r++)
#pragma unroll
                    for (int c = 0; c < 4; c++)
                        o[r][c] = fmaf(pr[r][kk], vb[c], o[r][c]);
            }
        }
        __syncthreads();
    }

    // normalize + store
#pragma unroll
    for (int r = 0; r < 4; r++) {
        float inv = 1.f / l[r];
        float* Op = O + base + (size_t)(q0 + tr*4 + r) * DM + tc*4;
        *(float4*)Op = make_float4(o[r][0]*inv, o[r][1]*inv, o[r][2]*inv, o[r][3]*inv);
    }
}

// ---------------- launch --------------------------------------------------------
extern "C" void kernel_launch(void* const* d_in, const int* in_sizes, int n_in,
                              void* d_out, int out_size) {
    (void)in_sizes; (void)n_in; (void)out_size;
    const float* gfeat = (const float*)d_in[0];
    const float* lfeat = (const float*)d_in[1];
    const float* tfeat = (const float*)d_in[2];
    const float* gqw = (const float*)d_in[3];  const float* gqb = (const float*)d_in[4];
    const float* gkw = (const float*)d_in[5];  const float* gkb = (const float*)d_in[6];
    const float* gvw = (const float*)d_in[7];  const float* gvb = (const float*)d_in[8];
    const float* pqw = (const float*)d_in[9];  const float* pqb = (const float*)d_in[10];
    const float* pkw = (const float*)d_in[11]; const float* pkb = (const float*)d_in[12];
    const float* pvw = (const float*)d_in[13]; const float* pvb = (const float*)d_in[14];
    const float* dw  = (const float*)d_in[15]; const float* db  = (const float*)d_in[16];
    float* out = (float*)d_out;

    float *gq, *gk, *gv, *pq, *pk, *pv, *att2, *ctx;
    cudaGetSymbolAddress((void**)&gq,   g_gq);
    cudaGetSymbolAddress((void**)&gk,   g_gk);
    cudaGetSymbolAddress((void**)&gv,   g_gv);
    cudaGetSymbolAddress((void**)&pq,   g_pq);
    cudaGetSymbolAddress((void**)&pk,   g_pk);
    cudaGetSymbolAddress((void**)&pv,   g_pv);
    cudaGetSymbolAddress((void**)&att2, g_att2);
    cudaGetSymbolAddress((void**)&ctx,  g_ctx);

    cudaFuncSetAttribute(attn_kernel, cudaFuncAttributeMaxDynamicSharedMemorySize, 65536);

    dim3 gg(DM/128, MT/128);   // (8, 32)

    // projections
    gemm_bias_kernel<<<gg, 256>>>(gfeat, gqw, gqb, gq);
    gemm_bias_kernel<<<gg, 256>>>(lfeat, gkw, gkb, gk);
    gemm_bias_kernel<<<gg, 256>>>(lfeat, gvw, gvb, gv);
    gemm_bias_kernel<<<gg, 256>>>(lfeat, pqw, pqb, pq);
    gemm_bias_kernel<<<gg, 256>>>(tfeat, pkw, pkb, pk);
    gemm_bias_kernel<<<gg, 256>>>(tfeat, pvw, pvb, pv);

    // att2 = softmax(pq pk^T / 8) @ pv
    // ctx  = softmax(gq gk^T / 8) @ (gv + att2)
    //   == glb_ctx + plb_ctx  (by matmul associativity; bridge GEMM eliminated)
    dim3 ga(SS/64, BB*NH);     // (16, 64)
    attn_kernel<<<ga, 256, 65536>>>(pq, pk, pv, nullptr, att2);
    attn_kernel<<<ga, 256, 65536>>>(gq, gk, att2, gv, ctx);

    // final dense
    gemm_bias_kernel<<<gg, 256>>>(ctx, dw, db, out);
}

// round 2
// speedup vs baseline: 1.6484x; 1.6484x over previous
#include <cuda_runtime.h>
#include <cstdint>

#define DM 1024     // d_model
#define NH 16       // heads
#define DH 64       // head dim
#define BB 4        // batch
#define SS 1024     // seq
#define MT (BB*SS)  // 4096 rows

// ---------------- scratch ----------------
__device__ float g_gq[MT*DM];
__device__ float g_gk[MT*DM];
__device__ float g_gv[MT*DM];
__device__ float g_pq[MT*DM];
__device__ float g_pk[MT*DM];
__device__ float g_pv[MT*DM];
__device__ float g_att2[MT*DM];
__device__ float g_ctx[MT*DM];

__device__ __forceinline__ float to_tf32(float x) {
    uint32_t u;
    asm("cvt.rna.tf32.f32 %0, %1;" : "=r"(u) : "f"(x));
    return __uint_as_float(u);
}

__device__ __forceinline__ void mma8(float* c,
    float a0, float a1, float a2, float a3, float b0, float b1) {
    asm volatile(
        "mma.sync.aligned.m16n8k8.row.col.f32.tf32.tf32.f32 "
        "{%0,%1,%2,%3},{%4,%5,%6,%7},{%8,%9},{%0,%1,%2,%3};\n"
        : "+f"(c[0]), "+f"(c[1]), "+f"(c[2]), "+f"(c[3])
        : "r"(__float_as_uint(a0)), "r"(__float_as_uint(a1)),
          "r"(__float_as_uint(a2)), "r"(__float_as_uint(a3)),
          "r"(__float_as_uint(b0)), "r"(__float_as_uint(b1)));
}

// ---------------- GEMM: C[4096,1024] = A @ W^T + bias (tf32 tensor core) -------
// 128x128 block, BK=32, 256 thr (8 warps, 2x4), warp tile 64x32.
// smem tiles stored [k][m] / [k][n], stride 136 (=8 mod 32 -> conflict-free frags)
#define GSTR 136
#define GBUF 4352   // 32*136
__global__ __launch_bounds__(256) void gemm_tc(
    const float* __restrict__ A, const float* __restrict__ W,
    const float* __restrict__ bias, float* __restrict__ C)
{
    extern __shared__ float sm[];
    float* As = sm;           // 2 * 4352
    float* Ws = sm + 2*GBUF;  // 2 * 4352

    const int tid  = threadIdx.x;
    const int wid  = tid >> 5, lane = tid & 31;
    const int g    = lane >> 2, tig = lane & 3;
    const int wm   = (wid >> 2) * 64, wn = (wid & 3) * 32;
    const int bm   = blockIdx.y << 7, bn = blockIdx.x << 7;
    const int ml   = tid & 127, kh = (tid >> 7) * 16;

    const float* Ap = A + (size_t)(bm + ml) * DM + kh;
    const float* Wp = W + (size_t)(bn + ml) * DM + kh;

    float acc[4][4][4];
#pragma unroll
    for (int i = 0; i < 4; i++)
#pragma unroll
        for (int j = 0; j < 4; j++)
#pragma unroll
            for (int e = 0; e < 4; e++) acc[i][j][e] = 0.f;

    float4 ar[4], wr[4];
#pragma unroll
    for (int c = 0; c < 4; c++) {
        ar[c] = *(const float4*)(Ap + 4*c);
        wr[c] = *(const float4*)(Wp + 4*c);
    }

    // STS buf 0
    {
        float* Ab = As; float* Wb = Ws;
#pragma unroll
        for (int c = 0; c < 4; c++) {
            int k = kh + 4*c;
            Ab[(k+0)*GSTR + ml] = to_tf32(ar[c].x);
            Ab[(k+1)*GSTR + ml] = to_tf32(ar[c].y);
            Ab[(k+2)*GSTR + ml] = to_tf32(ar[c].z);
            Ab[(k+3)*GSTR + ml] = to_tf32(ar[c].w);
            Wb[(k+0)*GSTR + ml] = to_tf32(wr[c].x);
            Wb[(k+1)*GSTR + ml] = to_tf32(wr[c].y);
            Wb[(k+2)*GSTR + ml] = to_tf32(wr[c].z);
            Wb[(k+3)*GSTR + ml] = to_tf32(wr[c].w);
        }
    }
    __syncthreads();

    int cur = 0;
    for (int kt = 0; kt < 32; kt++) {
        if (kt < 31) {
#pragma unroll
            for (int c = 0; c < 4; c++) {
                ar[c] = *(const float4*)(Ap + (kt+1)*32 + 4*c);
                wr[c] = *(const float4*)(Wp + (kt+1)*32 + 4*c);
            }
        }
        // compute from buf cur
        {
            const float* Ab = As + cur*GBUF;
            const float* Wb = Ws + cur*GBUF;
#pragma unroll
            for (int ks = 0; ks < 4; ks++) {
                const int kb = 8*ks;
                float a[4][4], b[4][2];
#pragma unroll
                for (int mt = 0; mt < 4; mt++) {
                    int mb = wm + 16*mt;
                    a[mt][0] = Ab[(kb+tig  )*GSTR + mb+g  ];
                    a[mt][1] = Ab[(kb+tig  )*GSTR + mb+g+8];
                    a[mt][2] = Ab[(kb+tig+4)*GSTR + mb+g  ];
                    a[mt][3] = Ab[(kb+tig+4)*GSTR + mb+g+8];
                }
#pragma unroll
                for (int nt = 0; nt < 4; nt++) {
                    int nb = wn + 8*nt;
                    b[nt][0] = Wb[(kb+tig  )*GSTR + nb+g];
                    b[nt][1] = Wb[(kb+tig+4)*GSTR + nb+g];
                }
#pragma unroll
                for (int mt = 0; mt < 4; mt++)
#pragma unroll
                    for (int nt = 0; nt < 4; nt++)
                        mma8(acc[mt][nt], a[mt][0], a[mt][1], a[mt][2], a[mt][3],
                             b[nt][0], b[nt][1]);
            }
        }
        if (kt < 31) {
            float* Ab = As + (cur^1)*GBUF;
            float* Wb = Ws + (cur^1)*GBUF;
#pragma unroll
            for (int c = 0; c < 4; c++) {
                int k = kh + 4*c;
                Ab[(k+0)*GSTR + ml] = to_tf32(ar[c].x);
                Ab[(k+1)*GSTR + ml] = to_tf32(ar[c].y);
                Ab[(k+2)*GSTR + ml] = to_tf32(ar[c].z);
                Ab[(k+3)*GSTR + ml] = to_tf32(ar[c].w);
                Wb[(k+0)*GSTR + ml] = to_tf32(wr[c].x);
                Wb[(k+1)*GSTR + ml] = to_tf32(wr[c].y);
                Wb[(k+2)*GSTR + ml] = to_tf32(wr[c].z);
                Wb[(k+3)*GSTR + ml] = to_tf32(wr[c].w);
            }
        }
        __syncthreads();
        cur ^= 1;
    }

    // epilogue
#pragma unroll
    for (int mt = 0; mt < 4; mt++) {
        int r0 = bm + wm + 16*mt + g;
#pragma unroll
        for (int nt = 0; nt < 4; nt++) {
            int c = bn + wn + 8*nt + 2*tig;
            float2 bv = *(const float2*)(bias + c);
            float2 o0 = make_float2(acc[mt][nt][0] + bv.x, acc[mt][nt][1] + bv.y);
            float2 o1 = make_float2(acc[mt][nt][2] + bv.x, acc[mt][nt][3] + bv.y);
            *(float2*)(C + (size_t)r0*DM + c)     = o0;
            *(float2*)(C + (size_t)(r0+8)*DM + c) = o1;
        }
    }
}

// ---------------- Flash attention, tf32 tensor core ----------------------------
// O = softmax(Q K^T / 8) @ (V + Vadd), 64q x 64k tiles, 128 thr (4 warps 2x2),
// warp tile 32x32. Qs/Ks stored [d][token], Vs [key][d], Ps [q][key]; stride 72.
#define ALD 72
__global__ __launch_bounds__(128) void attn_tc(
    const float* __restrict__ Q, const float* __restrict__ Kp,
    const float* __restrict__ V, const float* __restrict__ Vadd,
    float* __restrict__ O)
{
    extern __shared__ float sm[];
    float* Qs   = sm;            // 64*72
    float* Ks   = sm + 4608;
    float* Vs   = sm + 9216;
    float* Ps   = sm + 13824;
    float* al_s = sm + 18432;    // 64
    float* l_s  = sm + 18496;    // 64

    const int tid = threadIdx.x, wid = tid >> 5, lane = tid & 31;
    const int g = lane >> 2, tig = lane & 3;
    const int wm = (wid >> 1) * 32, wn = (wid & 1) * 32;
    const int q0 = blockIdx.x << 6;
    const int bh = blockIdx.y, b = bh >> 4, h = bh & 15;
    const size_t base = (size_t)b * SS * DM + (size_t)h * DH;

    const int row = tid >> 1, dh0 = (tid & 1) * 32;

    // load Q tile -> Qs[d][q] (tf32)
    {
        const float* qp = Q + base + (size_t)(q0 + row) * DM + dh0;
#pragma unroll
        for (int j = 0; j < 8; j++) {
            float4 v = *(const float4*)(qp + 4*j);
            int d = dh0 + 4*j;
            Qs[(d+0)*ALD + row] = to_tf32(v.x);
            Qs[(d+1)*ALD + row] = to_tf32(v.y);
            Qs[(d+2)*ALD + row] = to_tf32(v.z);
            Qs[(d+3)*ALD + row] = to_tf32(v.w);
        }
    }

    float o[2][4][4];
#pragma unroll
    for (int mt = 0; mt < 2; mt++)
#pragma unroll
        for (int nt = 0; nt < 4; nt++)
#pragma unroll
            for (int e = 0; e < 4; e++) o[mt][nt][e] = 0.f;
    float m_reg = -1e30f, l_reg = 0.f;

    for (int kt = 0; kt < 16; kt++) {
        const int k0 = kt << 6;
        __syncthreads();   // prior PV reads of Ks/Vs/Ps finished
        // load K -> Ks[d][key], V(+Vadd) -> Vs[key][d]
        {
            const float* kp = Kp + base + (size_t)(k0 + row) * DM + dh0;
            const float* vp = V  + base + (size_t)(k0 + row) * DM + dh0;
#pragma unroll
            for (int j = 0; j < 8; j++) {
                float4 kv = *(const float4*)(kp + 4*j);
                int d = dh0 + 4*j;
                Ks[(d+0)*ALD + row] = to_tf32(kv.x);
                Ks[(d+1)*ALD + row] = to_tf32(kv.y);
                Ks[(d+2)*ALD + row] = to_tf32(kv.z);
                Ks[(d+3)*ALD + row] = to_tf32(kv.w);
                float4 vv = *(const float4*)(vp + 4*j);
                if (Vadd) {
                    float4 av = *(const float4*)(Vadd + base + (size_t)(k0+row)*DM + dh0 + 4*j);
                    vv.x += av.x; vv.y += av.y; vv.z += av.z; vv.w += av.w;
                }
                vv.x = to_tf32(vv.x); vv.y = to_tf32(vv.y);
                vv.z = to_tf32(vv.z); vv.w = to_tf32(vv.w);
                *(float4*)(Vs + row*ALD + d) = vv;
            }
        }
        __syncthreads();

        // S = Q K^T (tf32 mma), write scaled into Ps[q][key]
        {
            float sc[2][4][4];
#pragma unroll
            for (int mt = 0; mt < 2; mt++)
#pragma unroll
                for (int nt = 0; nt < 4; nt++)
#pragma unroll
                    for (int e = 0; e < 4; e++) sc[mt][nt][e] = 0.f;
#pragma unroll
            for (int ks = 0; ks < 8; ks++) {
                const int kb = 8*ks;
                float a[2][4], bq[4][2];
#pragma unroll
                for (int mt = 0; mt < 2; mt++) {
                    int mb = wm + 16*mt;
                    a[mt][0] = Qs[(kb+tig  )*ALD + mb+g  ];
                    a[mt][1] = Qs[(kb+tig  )*ALD + mb+g+8];
                    a[mt][2] = Qs[(kb+tig+4)*ALD + mb+g  ];
                    a[mt][3] = Qs[(kb+tig+4)*ALD + mb+g+8];
                }
#pragma unroll
                for (int nt = 0; nt < 4; nt++) {
                    int nb = wn + 8*nt;
                    bq[nt][0] = Ks[(kb+tig  )*ALD + nb+g];
                    bq[nt][1] = Ks[(kb+tig+4)*ALD + nb+g];
                }
#pragma unroll
                for (int mt = 0; mt < 2; mt++)
#pragma unroll
                    for (int nt = 0; nt < 4; nt++)
                        mma8(sc[mt][nt], a[mt][0], a[mt][1], a[mt][2], a[mt][3],
                             bq[nt][0], bq[nt][1]);
            }
            const float scale = 0.125f;
#pragma unroll
            for (int mt = 0; mt < 2; mt++) {
                int r0 = wm + 16*mt + g;
#pragma unroll
                for (int nt = 0; nt < 4; nt++) {
                    int c = wn + 8*nt + 2*tig;
                    *(float2*)(Ps + r0*ALD + c) =
                        make_float2(sc[mt][nt][0]*scale, sc[mt][nt][1]*scale);
                    *(float2*)(Ps + (r0+8)*ALD + c) =
                        make_float2(sc[mt][nt][2]*scale, sc[mt][nt][3]*scale);
                }
            }
        }
        __syncthreads();

        // online softmax row pass: 2 threads per row, 32 cols each
        {
            float* pr = Ps + row*ALD + dh0;
            float4 v[8];
            float tm = -1e30f;
#pragma unroll
            for (int j = 0; j < 8; j++) {
                v[j] = *(const float4*)(pr + 4*j);
                tm = fmaxf(tm, fmaxf(fmaxf(v[j].x, v[j].y), fmaxf(v[j].z, v[j].w)));
            }
            tm = fmaxf(tm, __shfl_xor_sync(0xffffffffu, tm, 1));
            float mn = fmaxf(m_reg, tm);
            float al = __expf(m_reg - mn);
            float rs = 0.f;
#pragma unroll
            for (int j = 0; j < 8; j++) {
                v[j].x = __expf(v[j].x - mn); v[j].y = __expf(v[j].y - mn);
                v[j].z = __expf(v[j].z - mn); v[j].w = __expf(v[j].w - mn);
                rs += (v[j].x + v[j].y) + (v[j].z + v[j].w);
                *(float4*)(pr + 4*j) = v[j];
            }
            rs += __shfl_xor_sync(0xffffffffu, rs, 1);
            l_reg = l_reg * al + rs;
            m_reg = mn;
            if ((tid & 1) == 0) { al_s[row] = al; l_s[row] = l_reg; }
        }
        __syncthreads();

        // rescale O, then O += P @ V
#pragma unroll
        for (int mt = 0; mt < 2; mt++) {
            float alo = al_s[wm + 16*mt + g];
            float ahi = al_s[wm + 16*mt + g + 8];
#pragma unroll
            for (int nt = 0; nt < 4; nt++) {
                o[mt][nt][0] *= alo; o[mt][nt][1] *= alo;
                o[mt][nt][2] *= ahi; o[mt][nt][3] *= ahi;
            }
        }
#pragma unroll
        for (int ks = 0; ks < 8; ks++) {
            const int kb = 8*ks;
            float a[2][4], bv[4][2];
#pragma unroll
            for (int mt = 0; mt < 2; mt++) {
                int mb = wm + 16*mt;
                a[mt][0] = to_tf32(Ps[(mb+g  )*ALD + kb+tig  ]);
                a[mt][1] = to_tf32(Ps[(mb+g+8)*ALD + kb+tig  ]);
                a[mt][2] = to_tf32(Ps[(mb+g  )*ALD + kb+tig+4]);
                a[mt][3] = to_tf32(Ps[(mb+g+8)*ALD + kb+tig+4]);
            }
#pragma unroll
            for (int nt = 0; nt < 4; nt++) {
                int nb = wn + 8*nt;
                bv[nt][0] = Vs[(kb+tig  )*ALD + nb+g];
                bv[nt][1] = Vs[(kb+tig+4)*ALD + nb+g];
            }
#pragma unroll
            for (int mt = 0; mt < 2; mt++)
#pragma unroll
                for (int nt = 0; nt < 4; nt++)
                    mma8(o[mt][nt], a[mt][0], a[mt][1], a[mt][2], a[mt][3],
                         bv[nt][0], bv[nt][1]);
        }
    }
    __syncthreads();   // l_s final values visible

    // normalize + store
#pragma unroll
    for (int mt = 0; mt < 2; mt++) {
        int r0 = wm + 16*mt + g;
        float il0 = 1.f / l_s[r0];
        float il1 = 1.f / l_s[r0 + 8];
#pragma unroll
        for (int nt = 0; nt < 4; nt++) {
            int c = wn + 8*nt + 2*tig;
            *(float2*)(O + base + (size_t)(q0+r0)*DM + c) =
                make_float2(o[mt][nt][0]*il0, o[mt][nt][1]*il0);
            *(float2*)(O + base + (size_t)(q0+r0+8)*DM + c) =
                make_float2(o[mt][nt][2]*il1, o[mt][nt][3]*il1);
        }
    }
}

// ---------------- launch --------------------------------------------------------
extern "C" void kernel_launch(void* const* d_in, const int* in_sizes, int n_in,
                              void* d_out, int out_size) {
    (void)in_sizes; (void)n_in; (void)out_size;
    const float* gfeat = (const float*)d_in[0];
    const float* lfeat = (const float*)d_in[1];
    const float* tfeat = (const float*)d_in[2];
    const float* gqw = (const float*)d_in[3];  const float* gqb = (const float*)d_in[4];
    const float* gkw = (const float*)d_in[5];  const float* gkb = (const float*)d_in[6];
    const float* gvw = (const float*)d_in[7];  const float* gvb = (const float*)d_in[8];
    const float* pqw = (const float*)d_in[9];  const float* pqb = (const float*)d_in[10];
    const float* pkw = (const float*)d_in[11]; const float* pkb = (const float*)d_in[12];
    const float* pvw = (const float*)d_in[13]; const float* pvb = (const float*)d_in[14];
    const float* dw  = (const float*)d_in[15]; const float* db  = (const float*)d_in[16];
    float* out = (float*)d_out;

    float *gq, *gk, *gv, *pq, *pk, *pv, *att2, *ctx;
    cudaGetSymbolAddress((void**)&gq,   g_gq);
    cudaGetSymbolAddress((void**)&gk,   g_gk);
    cudaGetSymbolAddress((void**)&gv,   g_gv);
    cudaGetSymbolAddress((void**)&pq,   g_pq);
    cudaGetSymbolAddress((void**)&pk,   g_pk);
    cudaGetSymbolAddress((void**)&pv,   g_pv);
    cudaGetSymbolAddress((void**)&att2, g_att2);
    cudaGetSymbolAddress((void**)&ctx,  g_ctx);

    cudaFuncSetAttribute(gemm_tc, cudaFuncAttributeMaxDynamicSharedMemorySize, 69632);
    cudaFuncSetAttribute(attn_tc, cudaFuncAttributeMaxDynamicSharedMemorySize, 74240);

    dim3 gg(DM/128, MT/128);   // (8, 32)
    gemm_tc<<<gg, 256, 69632>>>(gfeat, gqw, gqb, gq);
    gemm_tc<<<gg, 256, 69632>>>(lfeat, gkw, gkb, gk);
    gemm_tc<<<gg, 256, 69632>>>(lfeat, gvw, gvb, gv);
    gemm_tc<<<gg, 256, 69632>>>(lfeat, pqw, pqb, pq);
    gemm_tc<<<gg, 256, 69632>>>(tfeat, pkw, pkb, pk);
    gemm_tc<<<gg, 256, 69632>>>(tfeat, pvw, pvb, pv);

    // att2 = softmax(pq pk^T/8) @ pv ; ctx = softmax(gq gk^T/8) @ (gv + att2)
    dim3 ga(SS/64, BB*NH);     // (16, 64)
    attn_tc<<<ga, 128, 74240>>>(pq, pk, pv, nullptr, att2);
    attn_tc<<<ga, 128, 74240>>>(gq, gk, att2, gv, ctx);

    gemm_tc<<<gg, 256, 69632>>>(ctx, dw, db, out);
}

// round 4
// speedup vs baseline: 2.2654x; 1.3743x over previous
#include <cuda_runtime.h>
#include <cstdint>

#define DM 1024     // d_model
#define NH 16       // heads
#define DH 64       // head dim
#define BB 4        // batch
#define SS 1024     // seq
#define MT (BB*SS)  // 4096 rows

// ---------------- scratch ----------------
__device__ float g_gq[MT*DM];
__device__ float g_gk[MT*DM];
__device__ float g_gv[MT*DM];
__device__ float g_pq[MT*DM];
__device__ float g_pk[MT*DM];
__device__ float g_pv[MT*DM];
__device__ float g_att2[MT*DM];
__device__ float g_ctx[MT*DM];
__device__ float g_at[DM*MT];   // A transposed+permuted [1024][4096]
__device__ float g_wt[DM*DM];   // W transposed+permuted [1024][1024]

__device__ __forceinline__ float to_tf32(float x) {
    uint32_t u;
    asm("cvt.rna.tf32.f32 %0, %1;" : "=r"(u) : "f"(x));
    return __uint_as_float(u);
}
__device__ __forceinline__ void mma8(float* c,
    float a0, float a1, float a2, float a3, float b0, float b1) {
    asm volatile(
        "mma.sync.aligned.m16n8k8.row.col.f32.tf32.tf32.f32 "
        "{%0,%1,%2,%3},{%4,%5,%6,%7},{%8,%9},{%0,%1,%2,%3};\n"
        : "+f"(c[0]), "+f"(c[1]), "+f"(c[2]), "+f"(c[3])
        : "r"(__float_as_uint(a0)), "r"(__float_as_uint(a1)),
          "r"(__float_as_uint(a2)), "r"(__float_as_uint(a3)),
          "r"(__float_as_uint(b0)), "r"(__float_as_uint(b1)));
}
__device__ __forceinline__ uint32_t smem_u32(const void* p) {
    uint32_t a;
    asm("{ .reg .u64 t; cvta.to.shared.u64 t, %1; cvt.u32.u64 %0, t; }" : "=r"(a) : "l"(p));
    return a;
}
__device__ __forceinline__ void cp16(uint32_t dst, const void* src) {
    asm volatile("cp.async.cg.shared.global [%0], [%1], 16;" :: "r"(dst), "l"(src) : "memory");
}

// ---------------- convert: transpose + tf32-round + fragment permutation --------
// in [Rm][1024] row-major -> out [1024][Rm], column permuted per 128-tile:
//  act (isW=0): sc = half*64 + hi*32 + g*4 + mt   <- m_local = half*64 + mt*16 + hi*8 + g
//  w   (isW=1): sc = chunk*32 + g*4 + nt          <- n_local = chunk*32 + nt*8 + g
__global__ __launch_bounds__(256) void conv_t(
    const float* __restrict__ in, float* __restrict__ out, int Rm, int isW)
{
    __shared__ float ts[128][33];
    const int m0 = blockIdx.x << 7, k0 = blockIdx.y << 5;
#pragma unroll
    for (int i = 0; i < 4; i++) {
        int idx = threadIdx.x + (i << 8);       // 0..1023
        int ml = idx >> 3, kc = (idx & 7) << 2;
        float4 v = *(const float4*)(in + (size_t)(m0 + ml) * 1024 + k0 + kc);
        ts[ml][kc]   = to_tf32(v.x); ts[ml][kc+1] = to_tf32(v.y);
        ts[ml][kc+2] = to_tf32(v.z); ts[ml][kc+3] = to_tf32(v.w);
    }
    __syncthreads();
#pragma unroll
    for (int i = 0; i < 16; i++) {
        int idx = threadIdx.x + (i << 8);       // 0..4095
        int kr = idx >> 7, sc = idx & 127;
        int ml;
        if (isW) {
            int ch = sc >> 5, r = sc & 31, gg = (r >> 2) & 7, nt = r & 3;
            ml = ch * 32 + nt * 8 + gg;
        } else {
            int hf = sc >> 6, r = sc & 63, hi = (r >> 5) & 1, gg = (r >> 2) & 7, mt = r & 3;
            ml = hf * 64 + mt * 16 + hi * 8 + gg;
        }
        out[(size_t)(k0 + kr) * Rm + m0 + sc] = ts[ml][kr];
    }
}

// ---------------- GEMM: C[4096,1024] = A @ W^T + bias (tf32 mma, cp.async) -----
// 128x128 tile, BK=32, 3 stages, 256 thr (8 warps 2x4), warp tile 64x32.
// smem row stride 136 floats -> all fragment LDS.128 conflict-free.
#define LDF 136
#define STG_F (32*LDF)       // 4352 floats per operand stage
#define STG_B (STG_F*4)      // 17408 bytes
#define GSMEM (3*2*STG_B)    // 104448

__global__ __launch_bounds__(256, 2) void gemm_tc2(
    const float* __restrict__ At, const float* __restrict__ Wt,
    const float* __restrict__ bias, float* __restrict__ C)
{
    extern __shared__ float sm[];
    const uint32_t sb = smem_u32(sm);
    const int tid = threadIdx.x, wid = tid >> 5, lane = tid & 31;
    const int g = lane >> 2, tig = lane & 3;
    const int half = wid >> 2, chw = wid & 3;
    const int bm = blockIdx.y << 7, bn = blockIdx.x << 7;

    float acc[4][4][4];
#pragma unroll
    for (int i = 0; i < 4; i++)
#pragma unroll
        for (int j = 0; j < 4; j++)
#pragma unroll
            for (int e = 0; e < 4; e++) acc[i][j][e] = 0.f;

    const int kr_l = tid >> 3;              // 0..31 (row for this thread's chunks)
    const int c_l  = tid & 7;               // chunk group

#define LOAD_STAGE(J, S) do { \
    uint32_t dstA = sb + (uint32_t)(S) * 2 * STG_B; \
    uint32_t dstW = dstA + STG_B; \
    const float* srA = At + (size_t)((J) * 32 + kr_l) * MT + bm; \
    const float* srW = Wt + (size_t)((J) * 32 + kr_l) * DM + bn; \
    _Pragma("unroll") \
    for (int ii = 0; ii < 4; ii++) { \
        int cc = c_l + ii * 8; \
        cp16(dstA + (uint32_t)kr_l * (LDF*4) + cc * 16, srA + cc * 4); \
        cp16(dstW + (uint32_t)kr_l * (LDF*4) + cc * 16, srW + cc * 4); \
    } \
    asm volatile("cp.async.commit_group;" ::: "memory"); \
} while (0)

    LOAD_STAGE(0, 0);
    LOAD_STAGE(1, 1);

    for (int j = 0; j < 32; j++) {
        if (j < 31) asm volatile("cp.async.wait_group 1;" ::: "memory");
        else        asm volatile("cp.async.wait_group 0;" ::: "memory");
        __syncthreads();

        const float* Ab = sm + (j % 3) * 2 * STG_F;
        const float* Wb = Ab + STG_F;
#pragma unroll
        for (int ks = 0; ks < 4; ks++) {
            const int kr0 = ks * 8 + tig;
            float a00[4], a10[4], a01[4], a11[4], b0[4], b1[4];
            *(float4*)a00 = *(const float4*)&Ab[kr0*LDF     + half*64      + g*4];
            *(float4*)a10 = *(const float4*)&Ab[kr0*LDF     + half*64 + 32 + g*4];
            *(float4*)a01 = *(const float4*)&Ab[(kr0+4)*LDF + half*64      + g*4];
            *(float4*)a11 = *(const float4*)&Ab[(kr0+4)*LDF + half*64 + 32 + g*4];
            *(float4*)b0  = *(const float4*)&Wb[kr0*LDF     + chw*32 + g*4];
            *(float4*)b1  = *(const float4*)&Wb[(kr0+4)*LDF + chw*32 + g*4];
#pragma unroll
            for (int mt = 0; mt < 4; mt++)
#pragma unroll
                for (int nt = 0; nt < 4; nt++)
                    mma8(acc[mt][nt], a00[mt], a10[mt], a01[mt], a11[mt],
                         b0[nt], b1[nt]);
        }
        if (j + 2 < 32) LOAD_STAGE(j + 2, (j + 2) % 3);
    }
#undef LOAD_STAGE

    // epilogue: rows bm + half*64 + mt*16 + g (+8); cols bn + chw*32 + nt*8 + 2*tig
#pragma unroll
    for (int mt = 0; mt < 4; mt++) {
        int r0 = bm + half * 64 + mt * 16 + g;
#pragma unroll
        for (int nt = 0; nt < 4; nt++) {
            int c = bn + chw * 32 + nt * 8 + 2 * tig;
            float2 bv = *(const float2*)(bias + c);
            *(float2*)(C + (size_t)r0 * DM + c) =
                make_float2(acc[mt][nt][0] + bv.x, acc[mt][nt][1] + bv.y);
            *(float2*)(C + (size_t)(r0 + 8) * DM + c) =
                make_float2(acc[mt][nt][2] + bv.x, acc[mt][nt][3] + bv.y);
        }
    }
}

// ---------------- Flash attention, tf32 tensor core (R2, proven) ----------------
#define ALD 72
__global__ __launch_bounds__(128) void attn_tc(
    const float* __restrict__ Q, const float* __restrict__ Kp,
    const float* __restrict__ V, const float* __restrict__ Vadd,
    float* __restrict__ O)
{
    extern __shared__ float sma[];
    float* Qs   = sma;
    float* Ks   = sma + 4608;
    float* Vs   = sma + 9216;
    float* Ps   = sma + 13824;
    float* al_s = sma + 18432;
    float* l_s  = sma + 18496;

    const int tid = threadIdx.x, wid = tid >> 5, lane = tid & 31;
    const int g = lane >> 2, tig = lane & 3;
    const int wm = (wid >> 1) * 32, wn = (wid & 1) * 32;
    const int q0 = blockIdx.x << 6;
    const int bh = blockIdx.y, b = bh >> 4, h = bh & 15;
    const size_t base = (size_t)b * SS * DM + (size_t)h * DH;

    const int row = tid >> 1, dh0 = (tid & 1) * 32;

    {
        const float* qp = Q + base + (size_t)(q0 + row) * DM + dh0;
#pragma unroll
        for (int j = 0; j < 8; j++) {
            float4 v = *(const float4*)(qp + 4*j);
            int d = dh0 + 4*j;
            Qs[(d+0)*ALD + row] = to_tf32(v.x);
            Qs[(d+1)*ALD + row] = to_tf32(v.y);
            Qs[(d+2)*ALD + row] = to_tf32(v.z);
            Qs[(d+3)*ALD + row] = to_tf32(v.w);
        }
    }

    float o[2][4][4];
#pragma unroll
    for (int mt = 0; mt < 2; mt++)
#pragma unroll
        for (int nt = 0; nt < 4; nt++)
#pragma unroll
            for (int e = 0; e < 4; e++) o[mt][nt][e] = 0.f;
    float m_reg = -1e30f, l_reg = 0.f;

    for (int kt = 0; kt < 16; kt++) {
        const int k0 = kt << 6;
        __syncthreads();
        {
            const float* kp = Kp + base + (size_t)(k0 + row) * DM + dh0;
            const float* vp = V  + base + (size_t)(k0 + row) * DM + dh0;
#pragma unroll
            for (int j = 0; j < 8; j++) {
                float4 kv = *(const float4*)(kp + 4*j);
                int d = dh0 + 4*j;
                Ks[(d+0)*ALD + row] = to_tf32(kv.x);
                Ks[(d+1)*ALD + row] = to_tf32(kv.y);
                Ks[(d+2)*ALD + row] = to_tf32(kv.z);
                Ks[(d+3)*ALD + row] = to_tf32(kv.w);
                float4 vv = *(const float4*)(vp + 4*j);
                if (Vadd) {
                    float4 av = *(const float4*)(Vadd + base + (size_t)(k0+row)*DM + dh0 + 4*j);
                    vv.x += av.x; vv.y += av.y; vv.z += av.z; vv.w += av.w;
                }
                vv.x = to_tf32(vv.x); vv.y = to_tf32(vv.y);
                vv.z = to_tf32(vv.z); vv.w = to_tf32(vv.w);
                *(float4*)(Vs + row*ALD + d) = vv;
            }
        }
        __syncthreads();

        {
            float sc[2][4][4];
#pragma unroll
            for (int mt = 0; mt < 2; mt++)
#pragma unroll
                for (int nt = 0; nt < 4; nt++)
#pragma unroll
                    for (int e = 0; e < 4; e++) sc[mt][nt][e] = 0.f;
#pragma unroll
            for (int ks = 0; ks < 8; ks++) {
                const int kb = 8*ks;
                float a[2][4], bq[4][2];
#pragma unroll
                for (int mt = 0; mt < 2; mt++) {
                    int mb = wm + 16*mt;
                    a[mt][0] = Qs[(kb+tig  )*ALD + mb+g  ];
                    a[mt][1] = Qs[(kb+tig  )*ALD + mb+g+8];
                    a[mt][2] = Qs[(kb+tig+4)*ALD + mb+g  ];
                    a[mt][3] = Qs[(kb+tig+4)*ALD + mb+g+8];
                }
#pragma unroll
                for (int nt = 0; nt < 4; nt++) {
                    int nb = wn + 8*nt;
                    bq[nt][0] = Ks[(kb+tig  )*ALD + nb+g];
                    bq[nt][1] = Ks[(kb+tig+4)*ALD + nb+g];
                }
#pragma unroll
                for (int mt = 0; mt < 2; mt++)
#pragma unroll
                    for (int nt = 0; nt < 4; nt++)
                        mma8(sc[mt][nt], a[mt][0], a[mt][1], a[mt][2], a[mt][3],
                             bq[nt][0], bq[nt][1]);
            }
            const float scale = 0.125f;
#pragma unroll
            for (int mt = 0; mt < 2; mt++) {
                int r0 = wm + 16*mt + g;
#pragma unroll
                for (int nt = 0; nt < 4; nt++) {
                    int c = wn + 8*nt + 2*tig;
                    *(float2*)(Ps + r0*ALD + c) =
                        make_float2(sc[mt][nt][0]*scale, sc[mt][nt][1]*scale);
                    *(float2*)(Ps + (r0+8)*ALD + c) =
                        make_float2(sc[mt][nt][2]*scale, sc[mt][nt][3]*scale);
                }
            }
        }
        __syncthreads();

        {
            float* pr = Ps + row*ALD + dh0;
            float4 v[8];
            float tm = -1e30f;
#pragma unroll
            for (int j = 0; j < 8; j++) {
                v[j] = *(const float4*)(pr + 4*j);
                tm = fmaxf(tm, fmaxf(fmaxf(v[j].x, v[j].y), fmaxf(v[j].z, v[j].w)));
            }
            tm = fmaxf(tm, __shfl_xor_sync(0xffffffffu, tm, 1));
            float mn = fmaxf(m_reg, tm);
            float al = __expf(m_reg - mn);
            float rs = 0.f;
#pragma unroll
            for (int j = 0; j < 8; j++) {
                v[j].x = __expf(v[j].x - mn); v[j].y = __expf(v[j].y - mn);
                v[j].z = __expf(v[j].z - mn); v[j].w = __expf(v[j].w - mn);
                rs += (v[j].x + v[j].y) + (v[j].z + v[j].w);
                *(float4*)(pr + 4*j) = v[j];
            }
            rs += __shfl_xor_sync(0xffffffffu, rs, 1);
            l_reg = l_reg * al + rs;
            m_reg = mn;
            if ((tid & 1) == 0) { al_s[row] = al; l_s[row] = l_reg; }
        }
        __syncthreads();

#pragma unroll
        for (int mt = 0; mt < 2; mt++) {
            float alo = al_s[wm + 16*mt + g];
            float ahi = al_s[wm + 16*mt + g + 8];
#pragma unroll
            for (int nt = 0; nt < 4; nt++) {
                o[mt][nt][0] *= alo; o[mt][nt][1] *= alo;
                o[mt][nt][2] *= ahi; o[mt][nt][3] *= ahi;
            }
        }
#pragma unroll
        for (int ks = 0; ks < 8; ks++) {
            const int kb = 8*ks;
            float a[2][4], bv[4][2];
#pragma unroll
            for (int mt = 0; mt < 2; mt++) {
                int mb = wm + 16*mt;
                a[mt][0] = to_tf32(Ps[(mb+g  )*ALD + kb+tig  ]);
                a[mt][1] = to_tf32(Ps[(mb+g+8)*ALD + kb+tig  ]);
                a[mt][2] = to_tf32(Ps[(mb+g  )*ALD + kb+tig+4]);
                a[mt][3] = to_tf32(Ps[(mb+g+8)*ALD + kb+tig+4]);
            }
#pragma unroll
            for (int nt = 0; nt < 4; nt++) {
                int nb = wn + 8*nt;
                bv[nt][0] = Vs[(kb+tig  )*ALD + nb+g];
                bv[nt][1] = Vs[(kb+tig+4)*ALD + nb+g];
            }
#pragma unroll
            for (int mt = 0; mt < 2; mt++)
#pragma unroll
                for (int nt = 0; nt < 4; nt++)
                    mma8(o[mt][nt], a[mt][0], a[mt][1], a[mt][2], a[mt][3],
                         bv[nt][0], bv[nt][1]);
        }
    }
    __syncthreads();

#pragma unroll
    for (int mt = 0; mt < 2; mt++) {
        int r0 = wm + 16*mt + g;
        float il0 = 1.f / l_s[r0];
        float il1 = 1.f / l_s[r0 + 8];
#pragma unroll
        for (int nt = 0; nt < 4; nt++) {
            int c = wn + 8*nt + 2*tig;
            *(float2*)(O + base + (size_t)(q0+r0)*DM + c) =
                make_float2(o[mt][nt][0]*il0, o[mt][nt][1]*il0);
            *(float2*)(O + base + (size_t)(q0+r0+8)*DM + c) =
                make_float2(o[mt][nt][2]*il1, o[mt][nt][3]*il1);
        }
    }
}

// ---------------- launch --------------------------------------------------------
extern "C" void kernel_launch(void* const* d_in, const int* in_sizes, int n_in,
                              void* d_out, int out_size) {
    (void)in_sizes; (void)n_in; (void)out_size;
    const float* gfeat = (const float*)d_in[0];
    const float* lfeat = (const float*)d_in[1];
    const float* tfeat = (const float*)d_in[2];
    const float* gqw = (const float*)d_in[3];  const float* gqb = (const float*)d_in[4];
    const float* gkw = (const float*)d_in[5];  const float* gkb = (const float*)d_in[6];
    const float* gvw = (const float*)d_in[7];  const float* gvb = (const float*)d_in[8];
    const float* pqw = (const float*)d_in[9];  const float* pqb = (const float*)d_in[10];
    const float* pkw = (const float*)d_in[11]; const float* pkb = (const float*)d_in[12];
    const float* pvw = (const float*)d_in[13]; const float* pvb = (const float*)d_in[14];
    const float* dw  = (const float*)d_in[15]; const float* db  = (const float*)d_in[16];
    float* out = (float*)d_out;

    float *gq, *gk, *gv, *pq, *pk, *pv, *att2, *ctx, *at, *wt;
    cudaGetSymbolAddress((void**)&gq,   g_gq);
    cudaGetSymbolAddress((void**)&gk,   g_gk);
    cudaGetSymbolAddress((void**)&gv,   g_gv);
    cudaGetSymbolAddress((void**)&pq,   g_pq);
    cudaGetSymbolAddress((void**)&pk,   g_pk);
    cudaGetSymbolAddress((void**)&pv,   g_pv);
    cudaGetSymbolAddress((void**)&att2, g_att2);
    cudaGetSymbolAddress((void**)&ctx,  g_ctx);
    cudaGetSymbolAddress((void**)&at,   g_at);
    cudaGetSymbolAddress((void**)&wt,   g_wt);

    cudaFuncSetAttribute(gemm_tc2, cudaFuncAttributeMaxDynamicSharedMemorySize, GSMEM);
    cudaFuncSetAttribute(attn_tc,  cudaFuncAttributeMaxDynamicSharedMemorySize, 74240);

    dim3 gg(DM/128, MT/128);   // (8, 32)
    dim3 ga(SS/64, BB*NH);     // (16, 64)
    dim3 gca(MT/128, DM/32);   // act convert (32, 32)
    dim3 gcw(DM/128, DM/32);   // weight convert (8, 32)

#define CONV_A(src)  conv_t<<<gca, 256>>>((src), at, MT, 0)
#define CONV_W(srcW) conv_t<<<gcw, 256>>>((srcW), wt, DM, 1)
#define GEMM(bias, dst) gemm_tc2<<<gg, 256, GSMEM>>>(at, wt, (bias), (dst))

    CONV_A(gfeat);
    CONV_W(gqw); GEMM(gqb, gq);
    CONV_A(lfeat);
    CONV_W(gkw); GEMM(gkb, gk);
    CONV_W(gvw); GEMM(gvb, gv);
    CONV_W(pqw); GEMM(pqb, pq);
    CONV_A(tfeat);
    CONV_W(pkw); GEMM(pkb, pk);
    CONV_W(pvw); GEMM(pvb, pv);

    // att2 = softmax(pq pk^T/8) @ pv ; ctx = softmax(gq gk^T/8) @ (gv + att2)
    attn_tc<<<ga, 128, 74240>>>(pq, pk, pv, nullptr, att2);
    attn_tc<<<ga, 128, 74240>>>(gq, gk, att2, gv, ctx);

    CONV_A(ctx);
    CONV_W(dw); GEMM(db, out);
#undef CONV_A
#undef CONV_W
#undef GEMM
}

// round 5
// speedup vs baseline: 2.5627x; 1.1312x over previous
#include <cuda_runtime.h>
#include <cstdint>

#define DM 1024     // d_model
#define NH 16       // heads
#define DH 64       // head dim
#define BB 4        // batch
#define SS 1024     // seq
#define MT (BB*SS)  // 4096 rows

// ---------------- scratch ----------------
__device__ float g_gq[MT*DM];
__device__ float g_gk[MT*DM];
__device__ float g_gv[MT*DM];
__device__ float g_pq[MT*DM];
__device__ float g_pk[MT*DM];
__device__ float g_pv[MT*DM];
__device__ float g_att2[MT*DM];
__device__ float g_ctx[MT*DM];
__device__ float g_at[DM*MT];   // A transposed+permuted [1024][4096]
__device__ float g_wt[DM*DM];   // W transposed+permuted [1024][1024]

__device__ __forceinline__ float to_tf32(float x) {
    uint32_t u;
    asm("cvt.rna.tf32.f32 %0, %1;" : "=r"(u) : "f"(x));
    return __uint_as_float(u);
}
__device__ __forceinline__ void mma8(float* c,
    float a0, float a1, float a2, float a3, float b0, float b1) {
    asm volatile(
        "mma.sync.aligned.m16n8k8.row.col.f32.tf32.tf32.f32 "
        "{%0,%1,%2,%3},{%4,%5,%6,%7},{%8,%9},{%0,%1,%2,%3};\n"
        : "+f"(c[0]), "+f"(c[1]), "+f"(c[2]), "+f"(c[3])
        : "r"(__float_as_uint(a0)), "r"(__float_as_uint(a1)),
          "r"(__float_as_uint(a2)), "r"(__float_as_uint(a3)),
          "r"(__float_as_uint(b0)), "r"(__float_as_uint(b1)));
}
__device__ __forceinline__ uint32_t smem_u32(const void* p) {
    uint32_t a;
    asm("{ .reg .u64 t; cvta.to.shared.u64 t, %1; cvt.u32.u64 %0, t; }" : "=r"(a) : "l"(p));
    return a;
}
__device__ __forceinline__ void cp16(uint32_t dst, const void* src) {
    asm volatile("cp.async.cg.shared.global [%0], [%1], 16;" :: "r"(dst), "l"(src) : "memory");
}

// ---------------- convert: transpose + tf32-round + fragment permutation --------
__global__ __launch_bounds__(256) void conv_t(
    const float* __restrict__ in, float* __restrict__ out, int Rm, int isW)
{
    __shared__ float ts[128][33];
    const int m0 = blockIdx.x << 7, k0 = blockIdx.y << 5;
#pragma unroll
    for (int i = 0; i < 4; i++) {
        int idx = threadIdx.x + (i << 8);
        int ml = idx >> 3, kc = (idx & 7) << 2;
        float4 v = *(const float4*)(in + (size_t)(m0 + ml) * 1024 + k0 + kc);
        ts[ml][kc]   = to_tf32(v.x); ts[ml][kc+1] = to_tf32(v.y);
        ts[ml][kc+2] = to_tf32(v.z); ts[ml][kc+3] = to_tf32(v.w);
    }
    __syncthreads();
#pragma unroll
    for (int i = 0; i < 16; i++) {
        int idx = threadIdx.x + (i << 8);
        int kr = idx >> 7, sc = idx & 127;
        int ml;
        if (isW) {
            int ch = sc >> 5, r = sc & 31, gg = (r >> 2) & 7, nt = r & 3;
            ml = ch * 32 + nt * 8 + gg;
        } else {
            int hf = sc >> 6, r = sc & 63, hi = (r >> 5) & 1, gg = (r >> 2) & 7, mt = r & 3;
            ml = hf * 64 + mt * 16 + hi * 8 + gg;
        }
        out[(size_t)(k0 + kr) * Rm + m0 + sc] = ts[ml][kr];
    }
}

// ---------------- GEMM (unchanged from R4) --------------------------------------
#define LDF 136
#define STG_F (32*LDF)
#define STG_B (STG_F*4)
#define GSMEM (3*2*STG_B)

__global__ __launch_bounds__(256, 2) void gemm_tc2(
    const float* __restrict__ At, const float* __restrict__ Wt,
    const float* __restrict__ bias, float* __restrict__ C)
{
    extern __shared__ float sm[];
    const uint32_t sb = smem_u32(sm);
    const int tid = threadIdx.x, wid = tid >> 5, lane = tid & 31;
    const int g = lane >> 2, tig = lane & 3;
    const int half = wid >> 2, chw = wid & 3;
    const int bm = blockIdx.y << 7, bn = blockIdx.x << 7;

    float acc[4][4][4];
#pragma unroll
    for (int i = 0; i < 4; i++)
#pragma unroll
        for (int j = 0; j < 4; j++)
#pragma unroll
            for (int e = 0; e < 4; e++) acc[i][j][e] = 0.f;

    const int kr_l = tid >> 3;
    const int c_l  = tid & 7;

#define LOAD_STAGE(J, S) do { \
    uint32_t dstA = sb + (uint32_t)(S) * 2 * STG_B; \
    uint32_t dstW = dstA + STG_B; \
    const float* srA = At + (size_t)((J) * 32 + kr_l) * MT + bm; \
    const float* srW = Wt + (size_t)((J) * 32 + kr_l) * DM + bn; \
    _Pragma("unroll") \
    for (int ii = 0; ii < 4; ii++) { \
        int cc = c_l + ii * 8; \
        cp16(dstA + (uint32_t)kr_l * (LDF*4) + cc * 16, srA + cc * 4); \
        cp16(dstW + (uint32_t)kr_l * (LDF*4) + cc * 16, srW + cc * 4); \
    } \
    asm volatile("cp.async.commit_group;" ::: "memory"); \
} while (0)

    LOAD_STAGE(0, 0);
    LOAD_STAGE(1, 1);

    for (int j = 0; j < 32; j++) {
        if (j < 31) asm volatile("cp.async.wait_group 1;" ::: "memory");
        else        asm volatile("cp.async.wait_group 0;" ::: "memory");
        __syncthreads();

        const float* Ab = sm + (j % 3) * 2 * STG_F;
        const float* Wb = Ab + STG_F;
#pragma unroll
        for (int ks = 0; ks < 4; ks++) {
            const int kr0 = ks * 8 + tig;
            float a00[4], a10[4], a01[4], a11[4], b0[4], b1[4];
            *(float4*)a00 = *(const float4*)&Ab[kr0*LDF     + half*64      + g*4];
            *(float4*)a10 = *(const float4*)&Ab[kr0*LDF     + half*64 + 32 + g*4];
            *(float4*)a01 = *(const float4*)&Ab[(kr0+4)*LDF + half*64      + g*4];
            *(float4*)a11 = *(const float4*)&Ab[(kr0+4)*LDF + half*64 + 32 + g*4];
            *(float4*)b0  = *(const float4*)&Wb[kr0*LDF     + chw*32 + g*4];
            *(float4*)b1  = *(const float4*)&Wb[(kr0+4)*LDF + chw*32 + g*4];
#pragma unroll
            for (int mt = 0; mt < 4; mt++)
#pragma unroll
                for (int nt = 0; nt < 4; nt++)
                    mma8(acc[mt][nt], a00[mt], a10[mt], a01[mt], a11[mt],
                         b0[nt], b1[nt]);
        }
        if (j + 2 < 32) LOAD_STAGE(j + 2, (j + 2) % 3);
    }
#undef LOAD_STAGE

#pragma unroll
    for (int mt = 0; mt < 4; mt++) {
        int r0 = bm + half * 64 + mt * 16 + g;
#pragma unroll
        for (int nt = 0; nt < 4; nt++) {
            int c = bn + chw * 32 + nt * 8 + 2 * tig;
            float2 bv = *(const float2*)(bias + c);
            *(float2*)(C + (size_t)r0 * DM + c) =
                make_float2(acc[mt][nt][0] + bv.x, acc[mt][nt][1] + bv.y);
            *(float2*)(C + (size_t)(r0 + 8) * DM + c) =
                make_float2(acc[mt][nt][2] + bv.x, acc[mt][nt][3] + bv.y);
        }
    }
}

// ---------------- Flash attention v2: 128q x 64k tiles, permuted fragments -----
// 256 thr, 8 warps: qg = wid>>2 (64 q rows each), kg = wid&3 (16 keys / 16 d).
// Qs [d][q'] (LDQ), Pt [key][q'] (LDQ), Ks [d][k'] (LDK), Vs [key][d'] (LDK).
//  q' perm: q = qg*64+mt*16+hi*8+g  <-> q' = qg*64+hi*32+g*4+mt
//  k'/d' perm: x = X16*16+nt*8+g    <-> x' = X16*16+g*2+nt
#define LDQ 136
#define LDK 72
#define ASMEM (26880*4)
__global__ __launch_bounds__(256, 2) void attn_tc2(
    const float* __restrict__ Q, const float* __restrict__ Kp,
    const float* __restrict__ V, const float* __restrict__ Vadd,
    float* __restrict__ O)
{
    extern __shared__ float sma[];
    float* Qs   = sma;            // 64*136 = 8704
    float* Pt   = sma + 8704;     // 64*136 = 8704
    float* Ks   = sma + 17408;    // 64*72  = 4608
    float* Vs   = sma + 22016;    // 64*72  = 4608
    float* al_s = sma + 26624;    // 128
    float* l_s  = sma + 26752;    // 128

    const int tid = threadIdx.x, wid = tid >> 5, lane = tid & 31;
    const int g = lane >> 2, tig = lane & 3;
    const int qg = wid >> 2, kg = wid & 3;
    const int q0 = blockIdx.x << 7;
    const int bh = blockIdx.y, b = bh >> 4, h = bh & 15;
    const size_t base = (size_t)b * SS * DM + (size_t)h * DH;

    // ---- load Q tile -> Qs[d][q'] (tf32, permuted) ----
    {
        int row = tid >> 1, dh = (tid & 1) << 5;
        int qs = (row & 64) | (((row >> 3) & 1) << 5) | ((row & 7) << 2) | ((row >> 4) & 3);
        const float* qp = Q + base + (size_t)(q0 + row) * DM + dh;
#pragma unroll
        for (int j = 0; j < 8; j++) {
            float4 v = *(const float4*)(qp + 4*j);
            int d = dh + 4*j;
            Qs[(d+0)*LDQ + qs] = to_tf32(v.x);
            Qs[(d+1)*LDQ + qs] = to_tf32(v.y);
            Qs[(d+2)*LDQ + qs] = to_tf32(v.z);
            Qs[(d+3)*LDQ + qs] = to_tf32(v.w);
        }
    }

    float oacc[4][2][4];
#pragma unroll
    for (int mt = 0; mt < 4; mt++)
#pragma unroll
        for (int nt = 0; nt < 2; nt++)
#pragma unroll
            for (int e = 0; e < 4; e++) oacc[mt][nt][e] = 0.f;
    float m_reg = -1e30f, l_reg = 0.f;

    const int lrow = tid >> 2, ldq = (tid & 3) << 4;   // K/V load: 64 rows, 16 d each
    const int kcol_st = (lrow & 48) | ((lrow & 7) << 1) | ((lrow >> 3) & 1);
    const int sq = tid >> 1, skh = (tid & 1) << 5;     // softmax: q' column, key half

    for (int kt = 0; kt < 16; kt++) {
        const int k0 = kt << 6;
        __syncthreads();   // prior PV done with Ks/Vs/Pt

        // ---- load K -> Ks[d][k'], V(+Vadd) -> Vs[key][d'] ----
        {
            const float* kp = Kp + base + (size_t)(k0 + lrow) * DM + ldq;
            const float* vp = V  + base + (size_t)(k0 + lrow) * DM + ldq;
#pragma unroll
            for (int j = 0; j < 4; j++) {
                float4 kv = *(const float4*)(kp + 4*j);
                int d = ldq + 4*j;
                Ks[(d+0)*LDK + kcol_st] = to_tf32(kv.x);
                Ks[(d+1)*LDK + kcol_st] = to_tf32(kv.y);
                Ks[(d+2)*LDK + kcol_st] = to_tf32(kv.z);
                Ks[(d+3)*LDK + kcol_st] = to_tf32(kv.w);
                float4 vv = *(const float4*)(vp + 4*j);
                if (Vadd) {
                    float4 av = *(const float4*)(Vadd + base + (size_t)(k0+lrow)*DM + ldq + 4*j);
                    vv.x += av.x; vv.y += av.y; vv.z += av.z; vv.w += av.w;
                }
                float c4[4] = {vv.x, vv.y, vv.z, vv.w};
#pragma unroll
                for (int e = 0; e < 4; e++) {
                    int dd = d + e;
                    int dc = (dd & 48) | ((dd & 7) << 1) | ((dd >> 3) & 1);
                    Vs[lrow*LDK + dc] = to_tf32(c4[e]);
                }
            }
        }
        __syncthreads();

        // ---- S = Q K^T (warp: 64q x 16k), store scaled to Pt[key][q'] ----
        {
            float sacc[4][2][4];
#pragma unroll
            for (int mt = 0; mt < 4; mt++)
#pragma unroll
                for (int nt = 0; nt < 2; nt++)
#pragma unroll
                    for (int e = 0; e < 4; e++) sacc[mt][nt][e] = 0.f;
#pragma unroll
            for (int ks = 0; ks < 8; ks++) {
                const int kb = ks * 8;
                float a00[4], a10[4], a01[4], a11[4], b0[2], b1[2];
                *(float4*)a00 = *(const float4*)&Qs[(kb+tig  )*LDQ + qg*64      + g*4];
                *(float4*)a10 = *(const float4*)&Qs[(kb+tig  )*LDQ + qg*64 + 32 + g*4];
                *(float4*)a01 = *(const float4*)&Qs[(kb+tig+4)*LDQ + qg*64      + g*4];
                *(float4*)a11 = *(const float4*)&Qs[(kb+tig+4)*LDQ + qg*64 + 32 + g*4];
                *(float2*)b0  = *(const float2*)&Ks[(kb+tig  )*LDK + kg*16 + g*2];
                *(float2*)b1  = *(const float2*)&Ks[(kb+tig+4)*LDK + kg*16 + g*2];
#pragma unroll
                for (int mt = 0; mt < 4; mt++)
#pragma unroll
                    for (int nt = 0; nt < 2; nt++)
                        mma8(sacc[mt][nt], a00[mt], a10[mt], a01[mt], a11[mt],
                             b0[nt], b1[nt]);
            }
            const float scale = 0.125f;
#pragma unroll
            for (int mt = 0; mt < 4; mt++) {
                int qsto = qg*64 + g*4 + mt;
#pragma unroll
                for (int nt = 0; nt < 2; nt++) {
                    int kc = kg*16 + nt*8 + 2*tig;
                    Pt[ kc   *LDQ + qsto     ] = sacc[mt][nt][0] * scale;
                    Pt[(kc+1)*LDQ + qsto     ] = sacc[mt][nt][1] * scale;
                    Pt[ kc   *LDQ + qsto + 32] = sacc[mt][nt][2] * scale;
                    Pt[(kc+1)*LDQ + qsto + 32] = sacc[mt][nt][3] * scale;
                }
            }
        }
        __syncthreads();

        // ---- online softmax on Pt columns (2 threads per q') ----
        {
            float tm = -1e30f;
#pragma unroll
            for (int k = 0; k < 32; k++)
                tm = fmaxf(tm, Pt[(skh+k)*LDQ + sq]);
            tm = fmaxf(tm, __shfl_xor_sync(0xffffffffu, tm, 1));
            float mn = fmaxf(m_reg, tm);
            float alv = __expf(m_reg - mn);
            float rs = 0.f;
#pragma unroll
            for (int k = 0; k < 32; k++) {
                float e = __expf(Pt[(skh+k)*LDQ + sq] - mn);
                rs += e;
                Pt[(skh+k)*LDQ + sq] = to_tf32(e);
            }
            rs += __shfl_xor_sync(0xffffffffu, rs, 1);
            l_reg = l_reg * alv + rs;
            m_reg = mn;
            if (!(tid & 1)) { al_s[sq] = alv; l_s[sq] = l_reg; }
        }
        __syncthreads();

        // ---- rescale O, then O += P V (warp: 64q x 16d) ----
        {
            float al0[4], al1[4];
            *(float4*)al0 = *(const float4*)&al_s[qg*64      + g*4];
            *(float4*)al1 = *(const float4*)&al_s[qg*64 + 32 + g*4];
#pragma unroll
            for (int mt = 0; mt < 4; mt++)
#pragma unroll
                for (int nt = 0; nt < 2; nt++) {
                    oacc[mt][nt][0] *= al0[mt]; oacc[mt][nt][1] *= al0[mt];
                    oacc[mt][nt][2] *= al1[mt]; oacc[mt][nt][3] *= al1[mt];
                }
#pragma unroll
            for (int ks = 0; ks < 8; ks++) {
                const int kb = ks * 8;
                float a00[4], a10[4], a01[4], a11[4], b0[2], b1[2];
                *(float4*)a00 = *(const float4*)&Pt[(kb+tig  )*LDQ + qg*64      + g*4];
                *(float4*)a10 = *(const float4*)&Pt[(kb+tig  )*LDQ + qg*64 + 32 + g*4];
                *(float4*)a01 = *(const float4*)&Pt[(kb+tig+4)*LDQ + qg*64      + g*4];
                *(float4*)a11 = *(const float4*)&Pt[(kb+tig+4)*LDQ + qg*64 + 32 + g*4];
                *(float2*)b0  = *(const float2*)&Vs[(kb+tig  )*LDK + kg*16 + g*2];
                *(float2*)b1  = *(const float2*)&Vs[(kb+tig+4)*LDK + kg*16 + g*2];
#pragma unroll
                for (int mt = 0; mt < 4; mt++)
#pragma unroll
                    for (int nt = 0; nt < 2; nt++)
                        mma8(oacc[mt][nt], a00[mt], a10[mt], a01[mt], a11[mt],
                             b0[nt], b1[nt]);
            }
        }
    }
    __syncthreads();

    // ---- normalize + store (un-permute q rows) ----
    {
        float l0[4], l1[4];
        *(float4*)l0 = *(const float4*)&l_s[qg*64      + g*4];
        *(float4*)l1 = *(const float4*)&l_s[qg*64 + 32 + g*4];
#pragma unroll
        for (int mt = 0; mt < 4; mt++) {
            float il0 = 1.f / l0[mt], il1 = 1.f / l1[mt];
            int qlo = q0 + qg*64 + mt*16 + g;
#pragma unroll
            for (int nt = 0; nt < 2; nt++) {
                int d0 = kg*16 + nt*8 + 2*tig;
                *(float2*)(O + base + (size_t)qlo * DM + d0) =
                    make_float2(oacc[mt][nt][0]*il0, oacc[mt][nt][1]*il0);
                *(float2*)(O + base + (size_t)(qlo+8) * DM + d0) =
                    make_float2(oacc[mt][nt][2]*il1, oacc[mt][nt][3]*il1);
            }
        }
    }
}

// ---------------- launch --------------------------------------------------------
extern "C" void kernel_launch(void* const* d_in, const int* in_sizes, int n_in,
                              void* d_out, int out_size) {
    (void)in_sizes; (void)n_in; (void)out_size;
    const float* gfeat = (const float*)d_in[0];
    const float* lfeat = (const float*)d_in[1];
    const float* tfeat = (const float*)d_in[2];
    const float* gqw = (const float*)d_in[3];  const float* gqb = (const float*)d_in[4];
    const float* gkw = (const float*)d_in[5];  const float* gkb = (const float*)d_in[6];
    const float* gvw = (const float*)d_in[7];  const float* gvb = (const float*)d_in[8];
    const float* pqw = (const float*)d_in[9];  const float* pqb = (const float*)d_in[10];
    const float* pkw = (const float*)d_in[11]; const float* pkb = (const float*)d_in[12];
    const float* pvw = (const float*)d_in[13]; const float* pvb = (const float*)d_in[14];
    const float* dw  = (const float*)d_in[15]; const float* db  = (const float*)d_in[16];
    float* out = (float*)d_out;

    float *gq, *gk, *gv, *pq, *pk, *pv, *att2, *ctx, *at, *wt;
    cudaGetSymbolAddress((void**)&gq,   g_gq);
    cudaGetSymbolAddress((void**)&gk,   g_gk);
    cudaGetSymbolAddress((void**)&gv,   g_gv);
    cudaGetSymbolAddress((void**)&pq,   g_pq);
    cudaGetSymbolAddress((void**)&pk,   g_pk);
    cudaGetSymbolAddress((void**)&pv,   g_pv);
    cudaGetSymbolAddress((void**)&att2, g_att2);
    cudaGetSymbolAddress((void**)&ctx,  g_ctx);
    cudaGetSymbolAddress((void**)&at,   g_at);
    cudaGetSymbolAddress((void**)&wt,   g_wt);

    cudaFuncSetAttribute(gemm_tc2, cudaFuncAttributeMaxDynamicSharedMemorySize, GSMEM);
    cudaFuncSetAttribute(attn_tc2, cudaFuncAttributeMaxDynamicSharedMemorySize, ASMEM);

    dim3 gg(DM/128, MT/128);   // (8, 32)
    dim3 ga(SS/128, BB*NH);    // (8, 64)
    dim3 gca(MT/128, DM/32);
    dim3 gcw(DM/128, DM/32);

#define CONV_A(src)  conv_t<<<gca, 256>>>((src), at, MT, 0)
#define CONV_W(srcW) conv_t<<<gcw, 256>>>((srcW), wt, DM, 1)
#define GEMM(bias, dst) gemm_tc2<<<gg, 256, GSMEM>>>(at, wt, (bias), (dst))

    CONV_A(gfeat);
    CONV_W(gqw); GEMM(gqb, gq);
    CONV_A(lfeat);
    CONV_W(gkw); GEMM(gkb, gk);
    CONV_W(gvw); GEMM(gvb, gv);
    CONV_W(pqw); GEMM(pqb, pq);
    CONV_A(tfeat);
    CONV_W(pkw); GEMM(pkb, pk);
    CONV_W(pvw); GEMM(pvb, pv);

    // att2 = softmax(pq pk^T/8) @ pv ; ctx = softmax(gq gk^T/8) @ (gv + att2)
    attn_tc2<<<ga, 256, ASMEM>>>(pq, pk, pv, nullptr, att2);
    attn_tc2<<<ga, 256, ASMEM>>>(gq, gk, att2, gv, ctx);

    CONV_A(ctx);
    CONV_W(dw); GEMM(db, out);
#undef CONV_A
#undef CONV_W
#undef GEMM
}

// round 6
// speedup vs baseline: 4.7446x; 1.8514x over previous
#include <cuda_runtime.h>
#include <cuda_fp16.h>
#include <cstdint>

#define DM 1024     // d_model
#define NH 16       // heads
#define DH 64       // head dim
#define BB 4        // batch
#define SS 1024     // seq
#define MT (BB*SS)  // 4096 rows

// ---------------- scratch ----------------
__device__ float g_gq[MT*DM];
__device__ float g_gk[MT*DM];
__device__ float g_gv[MT*DM];
__device__ float g_pq[MT*DM];
__device__ float g_pk[MT*DM];
__device__ float g_pv[MT*DM];
__device__ float g_att2[MT*DM];
__device__ float g_ctx[MT*DM];
__device__ __half2 g_at[(DM/2)*MT];   // A transposed+permuted+k-packed [512][4096]
__device__ __half2 g_wt[(DM/2)*DM];   // W transposed+permuted+k-packed [512][1024]

__device__ __forceinline__ void mma16(float* c,
    uint32_t a0, uint32_t a1, uint32_t a2, uint32_t a3, uint32_t b0, uint32_t b1) {
    asm volatile(
        "mma.sync.aligned.m16n8k16.row.col.f32.f16.f16.f32 "
        "{%0,%1,%2,%3},{%4,%5,%6,%7},{%8,%9},{%0,%1,%2,%3};\n"
        : "+f"(c[0]), "+f"(c[1]), "+f"(c[2]), "+f"(c[3])
        : "r"(a0), "r"(a1), "r"(a2), "r"(a3), "r"(b0), "r"(b1));
}
__device__ __forceinline__ uint32_t smem_u32(const void* p) {
    uint32_t a;
    asm("{ .reg .u64 t; cvta.to.shared.u64 t, %1; cvt.u32.u64 %0, t; }" : "=r"(a) : "l"(p));
    return a;
}
__device__ __forceinline__ void cp16(uint32_t dst, const void* src) {
    asm volatile("cp.async.cg.shared.global [%0], [%1], 16;" :: "r"(dst), "l"(src) : "memory");
}
__device__ __forceinline__ uint32_t packh2(float lo, float hi) {
    uint32_t r;
    asm("cvt.rn.f16x2.f32 %0, %1, %2;" : "=r"(r) : "f"(hi), "f"(lo));
    return r;
}

// ---------------- convert: transpose + fp16 + fragment permutation + k-pack ----
// in [Rm][1024] fp32 -> out half2 [512][Rm]; element [kp][m'] = (x[m][2kp], x[m][2kp+1])
//  act: m' = hf*64+hi*32+g*4+mt  <-> m = hf*64+mt*16+hi*8+g
//  w:   n' = ch*32+g*4+nt        <-> n = ch*32+nt*8+g
__global__ __launch_bounds__(256) void conv_t(
    const float* __restrict__ in, __half2* __restrict__ out, int Rm, int isW)
{
    __shared__ float ts[128][33];
    const int m0 = blockIdx.x << 7, k0 = blockIdx.y << 5;
#pragma unroll
    for (int i = 0; i < 4; i++) {
        int idx = threadIdx.x + (i << 8);
        int ml = idx >> 3, kc = (idx & 7) << 2;
        float4 v = *(const float4*)(in + (size_t)(m0 + ml) * 1024 + k0 + kc);
        ts[ml][kc] = v.x; ts[ml][kc+1] = v.y; ts[ml][kc+2] = v.z; ts[ml][kc+3] = v.w;
    }
    __syncthreads();
#pragma unroll
    for (int i = 0; i < 8; i++) {
        int idx = threadIdx.x + (i << 8);      // 0..2047
        int kp = idx >> 7, sc = idx & 127;
        int ml;
        if (isW) {
            int ch = sc >> 5, r = sc & 31, gg = (r >> 2) & 7, nt = r & 3;
            ml = ch * 32 + nt * 8 + gg;
        } else {
            int hf = sc >> 6, r = sc & 63, hi = (r >> 5) & 1, gg = (r >> 2) & 7, mt = r & 3;
            ml = hf * 64 + mt * 16 + hi * 8 + gg;
        }
        out[(size_t)((k0 >> 1) + kp) * Rm + m0 + sc] =
            __floats2half2_rn(ts[ml][2*kp], ts[ml][2*kp+1]);
    }
}

// ---------------- GEMM fp16: C[4096,1024] = A @ W^T + bias ---------------------
// 128x128 tile, BK=32 (16 half2 rows), 3 stages, 8 warps (2x4), warp 64x32.
#define LDH 136               // half2 row stride (8 mod 32 -> conflict-free)
#define STG_H2 (16*LDH)       // 2176 half2 per operand stage
#define STG_BY (STG_H2*4)     // 8704 bytes
#define GSMEM (3*2*STG_BY)    // 52224

__global__ __launch_bounds__(256, 2) void gemm_fp16(
    const __half2* __restrict__ At, const __half2* __restrict__ Wt,
    const float* __restrict__ bias, float* __restrict__ C)
{
    extern __shared__ __half2 smh[];
    const uint32_t sb = smem_u32(smh);
    const int tid = threadIdx.x, wid = tid >> 5, lane = tid & 31;
    const int g = lane >> 2, tig = lane & 3;
    const int half = wid >> 2, chw = wid & 3;
    const int bm = blockIdx.y << 7, bn = blockIdx.x << 7;

    float acc[4][4][4];
#pragma unroll
    for (int i = 0; i < 4; i++)
#pragma unroll
        for (int j = 0; j < 4; j++)
#pragma unroll
            for (int e = 0; e < 4; e++) acc[i][j][e] = 0.f;

#define LOAD_STAGE(J, S) do { \
    uint32_t dst = sb + (uint32_t)(S) * 2 * STG_BY; \
    _Pragma("unroll") \
    for (int p = 0; p < 2; p++) { \
        int ci = tid + (p << 8); \
        int row = ci >> 5, cc = ci & 31; \
        cp16(dst + row * (LDH*4) + cc * 16, \
             At + (size_t)((J) * 16 + row) * MT + bm + cc * 4); \
        cp16(dst + STG_BY + row * (LDH*4) + cc * 16, \
             Wt + (size_t)((J) * 16 + row) * DM + bn + cc * 4); \
    } \
    asm volatile("cp.async.commit_group;" ::: "memory"); \
} while (0)

    LOAD_STAGE(0, 0);
    LOAD_STAGE(1, 1);

    for (int j = 0; j < 32; j++) {
        if (j < 31) asm volatile("cp.async.wait_group 1;" ::: "memory");
        else        asm volatile("cp.async.wait_group 0;" ::: "memory");
        __syncthreads();

        const __half2* Ab = smh + (j % 3) * 2 * STG_H2;
        const __half2* Wb = Ab + STG_H2;
#pragma unroll
        for (int ks = 0; ks < 2; ks++) {
            const int kp0 = ks * 8 + tig;
            uint4 ua0 = *(const uint4*)&Ab[kp0*LDH     + half*64      + g*4];
            uint4 ua1 = *(const uint4*)&Ab[kp0*LDH     + half*64 + 32 + g*4];
            uint4 ua2 = *(const uint4*)&Ab[(kp0+4)*LDH + half*64      + g*4];
            uint4 ua3 = *(const uint4*)&Ab[(kp0+4)*LDH + half*64 + 32 + g*4];
            uint4 ub0 = *(const uint4*)&Wb[kp0*LDH     + chw*32 + g*4];
            uint4 ub1 = *(const uint4*)&Wb[(kp0+4)*LDH + chw*32 + g*4];
            const uint32_t a0[4] = {ua0.x, ua0.y, ua0.z, ua0.w};
            const uint32_t a1[4] = {ua1.x, ua1.y, ua1.z, ua1.w};
            const uint32_t a2[4] = {ua2.x, ua2.y, ua2.z, ua2.w};
            const uint32_t a3[4] = {ua3.x, ua3.y, ua3.z, ua3.w};
            const uint32_t b0[4] = {ub0.x, ub0.y, ub0.z, ub0.w};
            const uint32_t b1[4] = {ub1.x, ub1.y, ub1.z, ub1.w};
#pragma unroll
            for (int mt = 0; mt < 4; mt++)
#pragma unroll
                for (int nt = 0; nt < 4; nt++)
                    mma16(acc[mt][nt], a0[mt], a1[mt], a2[mt], a3[mt],
                          b0[nt], b1[nt]);
        }
        if (j + 2 < 32) LOAD_STAGE(j + 2, (j + 2) % 3);
    }
#undef LOAD_STAGE

#pragma unroll
    for (int mt = 0; mt < 4; mt++) {
        int r0 = bm + half * 64 + mt * 16 + g;
#pragma unroll
        for (int nt = 0; nt < 4; nt++) {
            int c = bn + chw * 32 + nt * 8 + 2 * tig;
            float2 bv = *(const float2*)(bias + c);
            *(float2*)(C + (size_t)r0 * DM + c) =
                make_float2(acc[mt][nt][0] + bv.x, acc[mt][nt][1] + bv.y);
            *(float2*)(C + (size_t)(r0 + 8) * DM + c) =
                make_float2(acc[mt][nt][2] + bv.x, acc[mt][nt][3] + bv.y);
        }
    }
}

// ---------------- Flash attention v3: fp16 mma, register softmax ----------------
// 256 thr, 8 warps; warp owns 16 q rows x all 64 keys (FA2 layout).
// Qs half2 [dp32][q128] (k-packed along d); Ks half2 [dp32][k'] with
// k' = (key&7)*8 + key>>3; Vs half2 [keypair32][d'] with d' = (d&7)*8 + d>>3.
// Softmax entirely in registers (quad shuffles); P packed to half2 in place.
#define LDQ2 136
#define LDK2 72
#define ASMEM ((32*LDQ2 + 2*32*LDK2)*4)   // 35840 bytes
__global__ __launch_bounds__(256, 2) void attn_fp16(
    const float* __restrict__ Q, const float* __restrict__ Kp,
    const float* __restrict__ V, const float* __restrict__ Vadd,
    float* __restrict__ O)
{
    extern __shared__ __half2 smh[];
    __half2* Qs = smh;                 // 32*136
    __half2* Ks = smh + 32*LDQ2;       // 32*72
    __half2* Vs = Ks  + 32*LDK2;       // 32*72

    const int tid = threadIdx.x, wid = tid >> 5, lane = tid & 31;
    const int g = lane >> 2, tig = lane & 3;
    const int wq = wid << 4;
    const int q0 = blockIdx.x << 7;
    const int bh = blockIdx.y, b = bh >> 4, h = bh & 15;
    const size_t base = (size_t)b * SS * DM + (size_t)h * DH;
    const float QSC = 0.125f * 1.44269504f;   // scale * log2(e)

    // ---- load Q -> Qs[dp][q] (scaled, fp16) ----
    {
        int row = tid >> 1, dh = (tid & 1) << 5;
        const float* qp = Q + base + (size_t)(q0 + row) * DM + dh;
#pragma unroll
        for (int j = 0; j < 8; j++) {
            float4 v = *(const float4*)(qp + 4*j);
            int dp = (dh >> 1) + 2*j;
            Qs[dp*LDQ2 + row]     = __floats2half2_rn(v.x*QSC, v.y*QSC);
            Qs[(dp+1)*LDQ2 + row] = __floats2half2_rn(v.z*QSC, v.w*QSC);
        }
    }

    float o[8][4];
#pragma unroll
    for (int nt = 0; nt < 8; nt++)
#pragma unroll
        for (int e = 0; e < 4; e++) o[nt][e] = 0.f;
    float m0 = -1e30f, m1 = -1e30f, l0 = 0.f, l1 = 0.f;

    const int kkey = tid & 63, kdh = (tid >> 6) << 4;           // K loader
    const int kc = ((kkey & 7) << 3) | (kkey >> 3);
    const int vkp = tid >> 3, vdg = (tid & 7) << 3;             // V loader

    for (int kt = 0; kt < 16; kt++) {
        const int k0 = kt << 6;
        __syncthreads();   // prior PV reads done

        // ---- K -> Ks[dp][k'] ----
        {
            const float* kptr = Kp + base + (size_t)(k0 + kkey) * DM + kdh;
#pragma unroll
            for (int j = 0; j < 4; j++) {
                float4 kv = *(const float4*)(kptr + 4*j);
                int dp = (kdh >> 1) + 2*j;
                Ks[dp*LDK2 + kc]     = __floats2half2_rn(kv.x, kv.y);
                Ks[(dp+1)*LDK2 + kc] = __floats2half2_rn(kv.z, kv.w);
            }
        }
        // ---- V(+Vadd) -> Vs[keypair][d'] ----
        {
            const float* v0 = V + base + (size_t)(k0 + 2*vkp) * DM + vdg;
            float va[8], vb[8];
            *(float4*)&va[0] = *(const float4*)v0;
            *(float4*)&va[4] = *(const float4*)(v0 + 4);
            *(float4*)&vb[0] = *(const float4*)(v0 + DM);
            *(float4*)&vb[4] = *(const float4*)(v0 + DM + 4);
            if (Vadd) {
                const float* a0 = Vadd + base + (size_t)(k0 + 2*vkp) * DM + vdg;
                float aa[8], ab[8];
                *(float4*)&aa[0] = *(const float4*)a0;
                *(float4*)&aa[4] = *(const float4*)(a0 + 4);
                *(float4*)&ab[0] = *(const float4*)(a0 + DM);
                *(float4*)&ab[4] = *(const float4*)(a0 + DM + 4);
#pragma unroll
                for (int e = 0; e < 8; e++) { va[e] += aa[e]; vb[e] += ab[e]; }
            }
#pragma unroll
            for (int e = 0; e < 8; e++)
                Vs[vkp*LDK2 + (e << 3) + (vdg >> 3)] = __floats2half2_rn(va[e], vb[e]);
        }
        __syncthreads();

        // ---- S = Q K^T : s[nt][4], rows (wq+g, wq+g+8), keys nt*8+2tig+{0,1} ----
        float s[8][4];
#pragma unroll
        for (int nt = 0; nt < 8; nt++)
#pragma unroll
            for (int e = 0; e < 4; e++) s[nt][e] = 0.f;
#pragma unroll
        for (int ks = 0; ks < 4; ks++) {
            const int dp0 = ks * 8 + tig;
            uint32_t a0 = *(const uint32_t*)&Qs[dp0*LDQ2 + wq + g];
            uint32_t a1 = *(const uint32_t*)&Qs[dp0*LDQ2 + wq + g + 8];
            uint32_t a2 = *(const uint32_t*)&Qs[(dp0+4)*LDQ2 + wq + g];
            uint32_t a3 = *(const uint32_t*)&Qs[(dp0+4)*LDQ2 + wq + g + 8];
            uint4 u0 = *(const uint4*)&Ks[dp0*LDK2 + g*8];
            uint4 u1 = *(const uint4*)&Ks[dp0*LDK2 + g*8 + 4];
            uint4 u2 = *(const uint4*)&Ks[(dp0+4)*LDK2 + g*8];
            uint4 u3 = *(const uint4*)&Ks[(dp0+4)*LDK2 + g*8 + 4];
            const uint32_t b0[8] = {u0.x,u0.y,u0.z,u0.w, u1.x,u1.y,u1.z,u1.w};
            const uint32_t b1[8] = {u2.x,u2.y,u2.z,u2.w, u3.x,u3.y,u3.z,u3.w};
#pragma unroll
            for (int nt = 0; nt < 8; nt++)
                mma16(s[nt], a0, a1, a2, a3, b0[nt], b1[nt]);
        }

        // ---- register online softmax (rows replicated across quad) ----
        float tm0 = -1e30f, tm1 = -1e30f;
#pragma unroll
        for (int nt = 0; nt < 8; nt++) {
            tm0 = fmaxf(tm0, fmaxf(s[nt][0], s[nt][1]));
            tm1 = fmaxf(tm1, fmaxf(s[nt][2], s[nt][3]));
        }
        tm0 = fmaxf(tm0, __shfl_xor_sync(0xffffffffu, tm0, 1));
        tm0 = fmaxf(tm0, __shfl_xor_sync(0xffffffffu, tm0, 2));
        tm1 = fmaxf(tm1, __shfl_xor_sync(0xffffffffu, tm1, 1));
        tm1 = fmaxf(tm1, __shfl_xor_sync(0xffffffffu, tm1, 2));
        float mn0 = fmaxf(m0, tm0), mn1 = fmaxf(m1, tm1);
        float al0 = exp2f(m0 - mn0), al1 = exp2f(m1 - mn1);
        float rs0 = 0.f, rs1 = 0.f;
        uint32_t p[4][4];
#pragma unroll
        for (int ks = 0; ks < 4; ks++) {
            float e00 = exp2f(s[2*ks][0]   - mn0), e01 = exp2f(s[2*ks][1]   - mn0);
            float e02 = exp2f(s[2*ks][2]   - mn1), e03 = exp2f(s[2*ks][3]   - mn1);
            float e10 = exp2f(s[2*ks+1][0] - mn0), e11 = exp2f(s[2*ks+1][1] - mn0);
            float e12 = exp2f(s[2*ks+1][2] - mn1), e13 = exp2f(s[2*ks+1][3] - mn1);
            rs0 += (e00 + e01) + (e10 + e11);
            rs1 += (e02 + e03) + (e12 + e13);
            p[ks][0] = packh2(e00, e01);
            p[ks][1] = packh2(e02, e03);
            p[ks][2] = packh2(e10, e11);
            p[ks][3] = packh2(e12, e13);
        }
        rs0 += __shfl_xor_sync(0xffffffffu, rs0, 1);
        rs0 += __shfl_xor_sync(0xffffffffu, rs0, 2);
        rs1 += __shfl_xor_sync(0xffffffffu, rs1, 1);
        rs1 += __shfl_xor_sync(0xffffffffu, rs1, 2);
        l0 = l0 * al0 + rs0;  m0 = mn0;
        l1 = l1 * al1 + rs1;  m1 = mn1;

        // ---- rescale O, then O += P V ----
#pragma unroll
        for (int nt = 0; nt < 8; nt++) {
            o[nt][0] *= al0; o[nt][1] *= al0;
            o[nt][2] *= al1; o[nt][3] *= al1;
        }
#pragma unroll
        for (int ks = 0; ks < 4; ks++) {
            const int kp0 = ks * 8 + tig;
            uint4 u0 = *(const uint4*)&Vs[kp0*LDK2 + g*8];
            uint4 u1 = *(const uint4*)&Vs[kp0*LDK2 + g*8 + 4];
            uint4 u2 = *(const uint4*)&Vs[(kp0+4)*LDK2 + g*8];
            uint4 u3 = *(const uint4*)&Vs[(kp0+4)*LDK2 + g*8 + 4];
            const uint32_t b0[8] = {u0.x,u0.y,u0.z,u0.w, u1.x,u1.y,u1.z,u1.w};
            const uint32_t b1[8] = {u2.x,u2.y,u2.z,u2.w, u3.x,u3.y,u3.z,u3.w};
#pragma unroll
            for (int nt = 0; nt < 8; nt++)
                mma16(o[nt], p[ks][0], p[ks][1], p[ks][2], p[ks][3],
                      b0[nt], b1[nt]);
        }
    }

    // ---- normalize + store ----
    {
        float il0 = 1.f / l0, il1 = 1.f / l1;
        int r = q0 + wq + g;
#pragma unroll
        for (int nt = 0; nt < 8; nt++) {
            int d0 = nt * 8 + 2 * tig;
            *(float2*)(O + base + (size_t)r * DM + d0) =
                make_float2(o[nt][0]*il0, o[nt][1]*il0);
            *(float2*)(O + base + (size_t)(r+8) * DM + d0) =
                make_float2(o[nt][2]*il1, o[nt][3]*il1);
        }
    }
}

// ---------------- launch --------------------------------------------------------
extern "C" void kernel_launch(void* const* d_in, const int* in_sizes, int n_in,
                              void* d_out, int out_size) {
    (void)in_sizes; (void)n_in; (void)out_size;
    const float* gfeat = (const float*)d_in[0];
    const float* lfeat = (const float*)d_in[1];
    const float* tfeat = (const float*)d_in[2];
    const float* gqw = (const float*)d_in[3];  const float* gqb = (const float*)d_in[4];
    const float* gkw = (const float*)d_in[5];  const float* gkb = (const float*)d_in[6];
    const float* gvw = (const float*)d_in[7];  const float* gvb = (const float*)d_in[8];
    const float* pqw = (const float*)d_in[9];  const float* pqb = (const float*)d_in[10];
    const float* pkw = (const float*)d_in[11]; const float* pkb = (const float*)d_in[12];
    const float* pvw = (const float*)d_in[13]; const float* pvb = (const float*)d_in[14];
    const float* dw  = (const float*)d_in[15]; const float* db  = (const float*)d_in[16];
    float* out = (float*)d_out;

    float *gq, *gk, *gv, *pq, *pk, *pv, *att2, *ctx;
    __half2 *at, *wt;
    cudaGetSymbolAddress((void**)&gq,   g_gq);
    cudaGetSymbolAddress((void**)&gk,   g_gk);
    cudaGetSymbolAddress((void**)&gv,   g_gv);
    cudaGetSymbolAddress((void**)&pq,   g_pq);
    cudaGetSymbolAddress((void**)&pk,   g_pk);
    cudaGetSymbolAddress((void**)&pv,   g_pv);
    cudaGetSymbolAddress((void**)&att2, g_att2);
    cudaGetSymbolAddress((void**)&ctx,  g_ctx);
    cudaGetSymbolAddress((void**)&at,   g_at);
    cudaGetSymbolAddress((void**)&wt,   g_wt);

    cudaFuncSetAttribute(gemm_fp16, cudaFuncAttributeMaxDynamicSharedMemorySize, GSMEM);

    dim3 gg(DM/128, MT/128);   // (8, 32)
    dim3 ga(SS/128, BB*NH);    // (8, 64)
    dim3 gca(MT/128, DM/32);   // (32, 32)
    dim3 gcw(DM/128, DM/32);   // (8, 32)

#define CONV_A(src)  conv_t<<<gca, 256>>>((src), at, MT, 0)
#define CONV_W(srcW) conv_t<<<gcw, 256>>>((srcW), wt, DM, 1)
#define GEMM(bias, dst) gemm_fp16<<<gg, 256, GSMEM>>>(at, wt, (bias), (dst))

    CONV_A(gfeat);
    CONV_W(gqw); GEMM(gqb, gq);
    CONV_A(lfeat);
    CONV_W(gkw); GEMM(gkb, gk);
    CONV_W(gvw); GEMM(gvb, gv);
    CONV_W(pqw); GEMM(pqb, pq);
    CONV_A(tfeat);
    CONV_W(pkw); GEMM(pkb, pk);
    CONV_W(pvw); GEMM(pvb, pv);

    // att2 = softmax(pq pk^T/8) @ pv ; ctx = softmax(gq gk^T/8) @ (gv + att2)
    attn_fp16<<<ga, 256, ASMEM>>>(pq, pk, pv, nullptr, att2);
    attn_fp16<<<ga, 256, ASMEM>>>(gq, gk, att2, gv, ctx);

    CONV_A(ctx);
    CONV_W(dw); GEMM(db, out);
#undef CONV_A
#undef CONV_W
#undef GEMM
}

// round 7
// speedup vs baseline: 4.9250x; 1.0380x over previous
#include <cuda_runtime.h>
#include <cuda_fp16.h>
#include <cstdint>

#define DM 1024     // d_model
#define NH 16       // heads
#define DH 64       // head dim
#define BB 4        // batch
#define SS 1024     // seq
#define MT (BB*SS)  // 4096 rows

// ---------------- scratch ----------------
__device__ float g_gq[MT*DM];
__device__ float g_gk[MT*DM];
__device__ float g_gv[MT*DM];
__device__ float g_pq[MT*DM];
__device__ float g_pk[MT*DM];
__device__ float g_pv[MT*DM];
__device__ float g_att2[MT*DM];
__device__ float g_ctx[MT*DM];
__device__ __half2 g_at[(DM/2)*MT];   // A transposed+permuted+k-packed [512][4096]
__device__ __half2 g_wt[(DM/2)*DM];   // W transposed+permuted+k-packed [512][1024]

__device__ __forceinline__ void mma16(float* c,
    uint32_t a0, uint32_t a1, uint32_t a2, uint32_t a3, uint32_t b0, uint32_t b1) {
    asm volatile(
        "mma.sync.aligned.m16n8k16.row.col.f32.f16.f16.f32 "
        "{%0,%1,%2,%3},{%4,%5,%6,%7},{%8,%9},{%0,%1,%2,%3};\n"
        : "+f"(c[0]), "+f"(c[1]), "+f"(c[2]), "+f"(c[3])
        : "r"(a0), "r"(a1), "r"(a2), "r"(a3), "r"(b0), "r"(b1));
}
__device__ __forceinline__ uint32_t smem_u32(const void* p) {
    uint32_t a;
    asm("{ .reg .u64 t; cvta.to.shared.u64 t, %1; cvt.u32.u64 %0, t; }" : "=r"(a) : "l"(p));
    return a;
}
__device__ __forceinline__ void cp16(uint32_t dst, const void* src) {
    asm volatile("cp.async.cg.shared.global [%0], [%1], 16;" :: "r"(dst), "l"(src) : "memory");
}
__device__ __forceinline__ uint32_t packh2(float lo, float hi) {
    uint32_t r;
    asm("cvt.rn.f16x2.f32 %0, %1, %2;" : "=r"(r) : "f"(hi), "f"(lo));
    return r;
}

// ---------------- convert: transpose + fp16 + fragment permutation + k-pack ----
__global__ __launch_bounds__(256) void conv_t(
    const float* __restrict__ in, __half2* __restrict__ out, int Rm, int isW)
{
    __shared__ float ts[128][33];
    const int m0 = blockIdx.x << 7, k0 = blockIdx.y << 5;
#pragma unroll
    for (int i = 0; i < 4; i++) {
        int idx = threadIdx.x + (i << 8);
        int ml = idx >> 3, kc = (idx & 7) << 2;
        float4 v = *(const float4*)(in + (size_t)(m0 + ml) * 1024 + k0 + kc);
        ts[ml][kc] = v.x; ts[ml][kc+1] = v.y; ts[ml][kc+2] = v.z; ts[ml][kc+3] = v.w;
    }
    __syncthreads();
#pragma unroll
    for (int i = 0; i < 8; i++) {
        int idx = threadIdx.x + (i << 8);      // 0..2047
        int kp = idx >> 7, sc = idx & 127;
        int ml;
        if (isW) {
            int ch = sc >> 5, r = sc & 31, gg = (r >> 2) & 7, nt = r & 3;
            ml = ch * 32 + nt * 8 + gg;
        } else {
            int hf = sc >> 6, r = sc & 63, hi = (r >> 5) & 1, gg = (r >> 2) & 7, mt = r & 3;
            ml = hf * 64 + mt * 16 + hi * 8 + gg;
        }
        out[(size_t)((k0 >> 1) + kp) * Rm + m0 + sc] =
            __floats2half2_rn(ts[ml][2*kp], ts[ml][2*kp+1]);
    }
}

// ---------------- GEMM fp16 v3: 4 warps, warp tile 64x64 -----------------------
// Block 128x128, BK=32 (16 half2 rows), 3-stage cp.async, 2 CTAs/SM.
// Per k16 step per warp: 8 LDS.128 + 32 HMMA (ratio 4:1).
#define LDH 136               // half2 row stride
#define STG_H2 (16*LDH)
#define STG_BY (STG_H2*4)     // 8704 bytes
#define GSMEM (3*2*STG_BY)    // 52224

__global__ __launch_bounds__(128, 2) void gemm_fp16(
    const __half2* __restrict__ At, const __half2* __restrict__ Wt,
    const float* __restrict__ bias, float* __restrict__ C)
{
    extern __shared__ __half2 smh[];
    const uint32_t sb = smem_u32(smh);
    const int tid = threadIdx.x, wid = tid >> 5, lane = tid & 31;
    const int g = lane >> 2, tig = lane & 3;
    const int wmh = (wid >> 1) * 64;   // A permuted-col base (m half)
    const int wnc = (wid & 1) * 64;    // W permuted-col base (2 chunks)
    const int bm = blockIdx.y << 7, bn = blockIdx.x << 7;

    float acc[4][8][4];
#pragma unroll
    for (int i = 0; i < 4; i++)
#pragma unroll
        for (int j = 0; j < 8; j++)
#pragma unroll
            for (int e = 0; e < 4; e++) acc[i][j][e] = 0.f;

#define LOAD_STAGE(J, S) do { \
    uint32_t dst = sb + (uint32_t)(S) * 2 * STG_BY; \
    _Pragma("unroll") \
    for (int p = 0; p < 4; p++) { \
        int ci = tid + (p << 7); \
        int row = ci >> 5, cc = ci & 31; \
        cp16(dst + row * (LDH*4) + cc * 16, \
             At + (size_t)((J) * 16 + row) * MT + bm + cc * 4); \
        cp16(dst + STG_BY + row * (LDH*4) + cc * 16, \
             Wt + (size_t)((J) * 16 + row) * DM + bn + cc * 4); \
    } \
    asm volatile("cp.async.commit_group;" ::: "memory"); \
} while (0)

    LOAD_STAGE(0, 0);
    LOAD_STAGE(1, 1);

    for (int j = 0; j < 32; j++) {
        if (j < 31) asm volatile("cp.async.wait_group 1;" ::: "memory");
        else        asm volatile("cp.async.wait_group 0;" ::: "memory");
        __syncthreads();

        const __half2* Ab = smh + (j % 3) * 2 * STG_H2;
        const __half2* Wb = Ab + STG_H2;
#pragma unroll
        for (int ks = 0; ks < 2; ks++) {
            const int kp0 = ks * 8 + tig;
            uint4 ua0 = *(const uint4*)&Ab[kp0*LDH     + wmh      + g*4];
            uint4 ua1 = *(const uint4*)&Ab[kp0*LDH     + wmh + 32 + g*4];
            uint4 ua2 = *(const uint4*)&Ab[(kp0+4)*LDH + wmh      + g*4];
            uint4 ua3 = *(const uint4*)&Ab[(kp0+4)*LDH + wmh + 32 + g*4];
            uint4 ub00 = *(const uint4*)&Wb[kp0*LDH     + wnc      + g*4];
            uint4 ub01 = *(const uint4*)&Wb[kp0*LDH     + wnc + 32 + g*4];
            uint4 ub10 = *(const uint4*)&Wb[(kp0+4)*LDH + wnc      + g*4];
            uint4 ub11 = *(const uint4*)&Wb[(kp0+4)*LDH + wnc + 32 + g*4];
            const uint32_t a0[4] = {ua0.x, ua0.y, ua0.z, ua0.w};
            const uint32_t a1[4] = {ua1.x, ua1.y, ua1.z, ua1.w};
            const uint32_t a2[4] = {ua2.x, ua2.y, ua2.z, ua2.w};
            const uint32_t a3[4] = {ua3.x, ua3.y, ua3.z, ua3.w};
            const uint32_t b0[8] = {ub00.x,ub00.y,ub00.z,ub00.w, ub01.x,ub01.y,ub01.z,ub01.w};
            const uint32_t b1[8] = {ub10.x,ub10.y,ub10.z,ub10.w, ub11.x,ub11.y,ub11.z,ub11.w};
#pragma unroll
            for (int mt = 0; mt < 4; mt++)
#pragma unroll
                for (int nt = 0; nt < 8; nt++)
                    mma16(acc[mt][nt], a0[mt], a1[mt], a2[mt], a3[mt],
                          b0[nt], b1[nt]);
        }
        if (j + 2 < 32) LOAD_STAGE(j + 2, (j + 2) % 3);
    }
#undef LOAD_STAGE

#pragma unroll
    for (int mt = 0; mt < 4; mt++) {
        int r0 = bm + (wid >> 1) * 64 + mt * 16 + g;
#pragma unroll
        for (int nt = 0; nt < 8; nt++) {
            int c = bn + (wid & 1) * 64 + (nt >> 2) * 32 + (nt & 3) * 8 + 2 * tig;
            float2 bv = *(const float2*)(bias + c);
            *(float2*)(C + (size_t)r0 * DM + c) =
                make_float2(acc[mt][nt][0] + bv.x, acc[mt][nt][1] + bv.y);
            *(float2*)(C + (size_t)(r0 + 8) * DM + c) =
                make_float2(acc[mt][nt][2] + bv.x, acc[mt][nt][3] + bv.y);
        }
    }
}

// ---------------- Flash attention v4: Q frags in regs, fused epilogue add ------
// O = softmax(Q K^T / 8) @ V  (+ Vpost added at store).
// 256 thr, 8 warps; warp owns 16 q rows x all 64 keys.
#define LDQ2 136
#define LDK2 72
#define ASMEM (2*32*LDK2*4)   // 18432 bytes (Q staging aliases Ks/Vs)
__global__ __launch_bounds__(256, 2) void attn_fp16(
    const float* __restrict__ Q, const float* __restrict__ Kp,
    const float* __restrict__ V, const float* __restrict__ Vpost,
    float* __restrict__ O)
{
    extern __shared__ __half2 smh[];
    __half2* Qs = smh;                 // staging (32*136 h2 = 17408B, aliased)
    __half2* Ks = smh;                 // 32*72
    __half2* Vs = smh + 32*LDK2;       // 32*72

    const int tid = threadIdx.x, wid = tid >> 5, lane = tid & 31;
    const int g = lane >> 2, tig = lane & 3;
    const int wq = wid << 4;
    const int q0 = blockIdx.x << 7;
    const int bh = blockIdx.y, b = bh >> 4, h = bh & 15;
    const size_t base = (size_t)b * SS * DM + (size_t)h * DH;
    const float QSC = 0.125f * 1.44269504f;   // scale * log2(e)

    // ---- stage Q -> Qs[dp][q] (scaled fp16), then extract per-warp fragments ----
    {
        int row = tid >> 1, dh = (tid & 1) << 5;
        const float* qp = Q + base + (size_t)(q0 + row) * DM + dh;
#pragma unroll
        for (int j = 0; j < 8; j++) {
            float4 v = *(const float4*)(qp + 4*j);
            int dp = (dh >> 1) + 2*j;
            Qs[dp*LDQ2 + row]     = __floats2half2_rn(v.x*QSC, v.y*QSC);
            Qs[(dp+1)*LDQ2 + row] = __floats2half2_rn(v.z*QSC, v.w*QSC);
        }
    }
    __syncthreads();
    uint32_t qa[4][4];
#pragma unroll
    for (int ks = 0; ks < 4; ks++) {
        const int dp0 = ks * 8 + tig;
        qa[ks][0] = *(const uint32_t*)&Qs[dp0*LDQ2 + wq + g];
        qa[ks][1] = *(const uint32_t*)&Qs[dp0*LDQ2 + wq + g + 8];
        qa[ks][2] = *(const uint32_t*)&Qs[(dp0+4)*LDQ2 + wq + g];
        qa[ks][3] = *(const uint32_t*)&Qs[(dp0+4)*LDQ2 + wq + g + 8];
    }

    float o[8][4];
#pragma unroll
    for (int nt = 0; nt < 8; nt++)
#pragma unroll
        for (int e = 0; e < 4; e++) o[nt][e] = 0.f;
    float m0 = -1e30f, m1 = -1e30f, l0 = 0.f, l1 = 0.f;

    const int kkey = tid & 63, kdh = (tid >> 6) << 4;           // K loader
    const int kc = ((kkey & 7) << 3) | (kkey >> 3);
    const int vkp = tid >> 3, vdg = (tid & 7) << 3;             // V loader

    for (int kt = 0; kt < 16; kt++) {
        const int k0 = kt << 6;
        __syncthreads();   // prior MMA reads done / Q frags extracted

        // ---- K -> Ks[dp][k'] ----
        {
            const float* kptr = Kp + base + (size_t)(k0 + kkey) * DM + kdh;
#pragma unroll
            for (int j = 0; j < 4; j++) {
                float4 kv = *(const float4*)(kptr + 4*j);
                int dp = (kdh >> 1) + 2*j;
                Ks[dp*LDK2 + kc]     = __floats2half2_rn(kv.x, kv.y);
                Ks[(dp+1)*LDK2 + kc] = __floats2half2_rn(kv.z, kv.w);
            }
        }
        // ---- V -> Vs[keypair][d'] ----
        {
            const float* v0 = V + base + (size_t)(k0 + 2*vkp) * DM + vdg;
            float va[8], vb[8];
            *(float4*)&va[0] = *(const float4*)v0;
            *(float4*)&va[4] = *(const float4*)(v0 + 4);
            *(float4*)&vb[0] = *(const float4*)(v0 + DM);
            *(float4*)&vb[4] = *(const float4*)(v0 + DM + 4);
#pragma unroll
            for (int e = 0; e < 8; e++)
                Vs[vkp*LDK2 + (e << 3) + (vdg >> 3)] = __floats2half2_rn(va[e], vb[e]);
        }
        __syncthreads();

        // ---- S = Q K^T ----
        float s[8][4];
#pragma unroll
        for (int nt = 0; nt < 8; nt++)
#pragma unroll
            for (int e = 0; e < 4; e++) s[nt][e] = 0.f;
#pragma unroll
        for (int ks = 0; ks < 4; ks++) {
            const int dp0 = ks * 8 + tig;
            uint4 u0 = *(const uint4*)&Ks[dp0*LDK2 + g*8];
            uint4 u1 = *(const uint4*)&Ks[dp0*LDK2 + g*8 + 4];
            uint4 u2 = *(const uint4*)&Ks[(dp0+4)*LDK2 + g*8];
            uint4 u3 = *(const uint4*)&Ks[(dp0+4)*LDK2 + g*8 + 4];
            const uint32_t b0[8] = {u0.x,u0.y,u0.z,u0.w, u1.x,u1.y,u1.z,u1.w};
            const uint32_t b1[8] = {u2.x,u2.y,u2.z,u2.w, u3.x,u3.y,u3.z,u3.w};
#pragma unroll
            for (int nt = 0; nt < 8; nt++)
                mma16(s[nt], qa[ks][0], qa[ks][1], qa[ks][2], qa[ks][3],
                      b0[nt], b1[nt]);
        }

        // ---- register online softmax ----
        float tm0 = -1e30f, tm1 = -1e30f;
#pragma unroll
        for (int nt = 0; nt < 8; nt++) {
            tm0 = fmaxf(tm0, fmaxf(s[nt][0], s[nt][1]));
            tm1 = fmaxf(tm1, fmaxf(s[nt][2], s[nt][3]));
        }
        tm0 = fmaxf(tm0, __shfl_xor_sync(0xffffffffu, tm0, 1));
        tm0 = fmaxf(tm0, __shfl_xor_sync(0xffffffffu, tm0, 2));
        tm1 = fmaxf(tm1, __shfl_xor_sync(0xffffffffu, tm1, 1));
        tm1 = fmaxf(tm1, __shfl_xor_sync(0xffffffffu, tm1, 2));
        float mn0 = fmaxf(m0, tm0), mn1 = fmaxf(m1, tm1);
        float al0 = exp2f(m0 - mn0), al1 = exp2f(m1 - mn1);
        float rs0 = 0.f, rs1 = 0.f;
        uint32_t p[4][4];
#pragma unroll
        for (int ks = 0; ks < 4; ks++) {
            float e00 = exp2f(s[2*ks][0]   - mn0), e01 = exp2f(s[2*ks][1]   - mn0);
            float e02 = exp2f(s[2*ks][2]   - mn1), e03 = exp2f(s[2*ks][3]   - mn1);
            float e10 = exp2f(s[2*ks+1][0] - mn0), e11 = exp2f(s[2*ks+1][1] - mn0);
            float e12 = exp2f(s[2*ks+1][2] - mn1), e13 = exp2f(s[2*ks+1][3] - mn1);
            rs0 += (e00 + e01) + (e10 + e11);
            rs1 += (e02 + e03) + (e12 + e13);
            p[ks][0] = packh2(e00, e01);
            p[ks][1] = packh2(e02, e03);
            p[ks][2] = packh2(e10, e11);
            p[ks][3] = packh2(e12, e13);
        }
        rs0 += __shfl_xor_sync(0xffffffffu, rs0, 1);
        rs0 += __shfl_xor_sync(0xffffffffu, rs0, 2);
        rs1 += __shfl_xor_sync(0xffffffffu, rs1, 1);
        rs1 += __shfl_xor_sync(0xffffffffu, rs1, 2);
        l0 = l0 * al0 + rs0;  m0 = mn0;
        l1 = l1 * al1 + rs1;  m1 = mn1;

        // ---- rescale O, then O += P V ----
#pragma unroll
        for (int nt = 0; nt < 8; nt++) {
            o[nt][0] *= al0; o[nt][1] *= al0;
            o[nt][2] *= al1; o[nt][3] *= al1;
        }
#pragma unroll
        for (int ks = 0; ks < 4; ks++) {
            const int kp0 = ks * 8 + tig;
            uint4 u0 = *(const uint4*)&Vs[kp0*LDK2 + g*8];
            uint4 u1 = *(const uint4*)&Vs[kp0*LDK2 + g*8 + 4];
            uint4 u2 = *(const uint4*)&Vs[(kp0+4)*LDK2 + g*8];
            uint4 u3 = *(const uint4*)&Vs[(kp0+4)*LDK2 + g*8 + 4];
            const uint32_t b0[8] = {u0.x,u0.y,u0.z,u0.w, u1.x,u1.y,u1.z,u1.w};
            const uint32_t b1[8] = {u2.x,u2.y,u2.z,u2.w, u3.x,u3.y,u3.z,u3.w};
#pragma unroll
            for (int nt = 0; nt < 8; nt++)
                mma16(o[nt], p[ks][0], p[ks][1], p[ks][2], p[ks][3],
                      b0[nt], b1[nt]);
        }
    }

    // ---- normalize (+Vpost) + store ----
    {
        float il0 = 1.f / l0, il1 = 1.f / l1;
        int r = q0 + wq + g;
#pragma unroll
        for (int nt = 0; nt < 8; nt++) {
            int d0 = nt * 8 + 2 * tig;
            float2 o0 = make_float2(o[nt][0]*il0, o[nt][1]*il0);
            float2 o1 = make_float2(o[nt][2]*il1, o[nt][3]*il1);
            if (Vpost) {
                float2 v0 = *(const float2*)(Vpost + base + (size_t)r * DM + d0);
                float2 v1 = *(const float2*)(Vpost + base + (size_t)(r+8) * DM + d0);
                o0.x += v0.x; o0.y += v0.y; o1.x += v1.x; o1.y += v1.y;
            }
            *(float2*)(O + base + (size_t)r * DM + d0)     = o0;
            *(float2*)(O + base + (size_t)(r+8) * DM + d0) = o1;
        }
    }
}

// ---------------- launch --------------------------------------------------------
extern "C" void kernel_launch(void* const* d_in, const int* in_sizes, int n_in,
                              void* d_out, int out_size) {
    (void)in_sizes; (void)n_in; (void)out_size;
    const float* gfeat = (const float*)d_in[0];
    const float* lfeat = (const float*)d_in[1];
    const float* tfeat = (const float*)d_in[2];
    const float* gqw = (const float*)d_in[3];  const float* gqb = (const float*)d_in[4];
    const float* gkw = (const float*)d_in[5];  const float* gkb = (const float*)d_in[6];
    const float* gvw = (const float*)d_in[7];  const float* gvb = (const float*)d_in[8];
    const float* pqw = (const float*)d_in[9];  const float* pqb = (const float*)d_in[10];
    const float* pkw = (const float*)d_in[11]; const float* pkb = (const float*)d_in[12];
    const float* pvw = (const float*)d_in[13]; const float* pvb = (const float*)d_in[14];
    const float* dw  = (const float*)d_in[15]; const float* db  = (const float*)d_in[16];
    float* out = (float*)d_out;

    float *gq, *gk, *gv, *pq, *pk, *pv, *att2, *ctx;
    __half2 *at, *wt;
    cudaGetSymbolAddress((void**)&gq,   g_gq);
    cudaGetSymbolAddress((void**)&gk,   g_gk);
    cudaGetSymbolAddress((void**)&gv,   g_gv);
    cudaGetSymbolAddress((void**)&pq,   g_pq);
    cudaGetSymbolAddress((void**)&pk,   g_pk);
    cudaGetSymbolAddress((void**)&pv,   g_pv);
    cudaGetSymbolAddress((void**)&att2, g_att2);
    cudaGetSymbolAddress((void**)&ctx,  g_ctx);
    cudaGetSymbolAddress((void**)&at,   g_at);
    cudaGetSymbolAddress((void**)&wt,   g_wt);

    cudaFuncSetAttribute(gemm_fp16, cudaFuncAttributeMaxDynamicSharedMemorySize, GSMEM);

    dim3 gg(DM/128, MT/128);   // (8, 32)
    dim3 ga(SS/128, BB*NH);    // (8, 64)
    dim3 gca(MT/128, DM/32);   // (32, 32)
    dim3 gcw(DM/128, DM/32);   // (8, 32)

#define CONV_A(src)  conv_t<<<gca, 256>>>((src), at, MT, 0)
#define CONV_W(srcW) conv_t<<<gcw, 256>>>((srcW), wt, DM, 1)
#define GEMM(bias, dst) gemm_fp16<<<gg, 128, GSMEM>>>(at, wt, (bias), (dst))

    CONV_A(gfeat);
    CONV_W(gqw); GEMM(gqb, gq);
    CONV_A(lfeat);
    CONV_W(gkw); GEMM(gkb, gk);
    CONV_W(gvw); GEMM(gvb, gv);
    CONV_W(pqw); GEMM(pqb, pq);
    CONV_A(tfeat);
    CONV_W(pkw); GEMM(pkb, pk);
    CONV_W(pvw); GEMM(pvb, pv);

    // att2pg = softmax(pq pk^T/8) @ pv + gv   (stored in g_att2)
    // ctx    = softmax(gq gk^T/8) @ att2pg
    attn_fp16<<<ga, 256, ASMEM>>>(pq, pk, pv, gv, att2);
    attn_fp16<<<ga, 256, ASMEM>>>(gq, gk, att2, nullptr, ctx);

    CONV_A(ctx);
    CONV_W(dw); GEMM(db, out);
#undef CONV_A
#undef CONV_W
#undef GEMM
}

// round 8
// speedup vs baseline: 5.5330x; 1.1235x over previous
#include <cuda_runtime.h>
#include <cuda_fp16.h>
#include <cstdint>

#define DM 1024     // d_model
#define NH 16       // heads
#define DH 64       // head dim
#define BB 4        // batch
#define SS 1024     // seq
#define MT (BB*SS)  // 4096 rows

// ---------------- scratch ----------------
__device__ __half g_qh[MT*DM];     // gq
__device__ __half g_kh[MT*DM];     // gk
__device__ __half g_vh[MT*DM];     // gv
__device__ __half g_pqh[MT*DM];
__device__ __half g_pkh[MT*DM];
__device__ __half g_pvh[MT*DM];
__device__ __half g_a2h[MT*DM];    // att2 + gv
__device__ __half2 g_at[(DM/2)*MT];   // A transposed+permuted+k-packed [512][4096]
__device__ __half2 g_wt[(DM/2)*DM];   // W transposed+permuted+k-packed [512][1024]

__device__ __forceinline__ void mma16(float* c,
    uint32_t a0, uint32_t a1, uint32_t a2, uint32_t a3, uint32_t b0, uint32_t b1) {
    asm volatile(
        "mma.sync.aligned.m16n8k16.row.col.f32.f16.f16.f32 "
        "{%0,%1,%2,%3},{%4,%5,%6,%7},{%8,%9},{%0,%1,%2,%3};\n"
        : "+f"(c[0]), "+f"(c[1]), "+f"(c[2]), "+f"(c[3])
        : "r"(a0), "r"(a1), "r"(a2), "r"(a3), "r"(b0), "r"(b1));
}
__device__ __forceinline__ uint32_t smem_u32(const void* p) {
    uint32_t a;
    asm("{ .reg .u64 t; cvta.to.shared.u64 t, %1; cvt.u32.u64 %0, t; }" : "=r"(a) : "l"(p));
    return a;
}
__device__ __forceinline__ void cp16(uint32_t dst, const void* src) {
    asm volatile("cp.async.cg.shared.global [%0], [%1], 16;" :: "r"(dst), "l"(src) : "memory");
}
__device__ __forceinline__ uint32_t packh2(float lo, float hi) {
    uint32_t r;
    asm("cvt.rn.f16x2.f32 %0, %1, %2;" : "=r"(r) : "f"(hi), "f"(lo));
    return r;
}
__device__ __forceinline__ uint32_t prmt(uint32_t a, uint32_t b, uint32_t s) {
    uint32_t d;
    asm("prmt.b32 %0, %1, %2, %3;" : "=r"(d) : "r"(a), "r"(b), "r"(s));
    return d;
}

// ---------------- convert: fp32 in -> half2 transposed+permuted+k-packed -------
__global__ __launch_bounds__(256) void conv_t(
    const float* __restrict__ in, __half2* __restrict__ out, int Rm, int isW)
{
    __shared__ float ts[128][33];
    const int m0 = blockIdx.x << 7, k0 = blockIdx.y << 5;
#pragma unroll
    for (int i = 0; i < 4; i++) {
        int idx = threadIdx.x + (i << 8);
        int ml = idx >> 3, kc = (idx & 7) << 2;
        float4 v = *(const float4*)(in + (size_t)(m0 + ml) * 1024 + k0 + kc);
        ts[ml][kc] = v.x; ts[ml][kc+1] = v.y; ts[ml][kc+2] = v.z; ts[ml][kc+3] = v.w;
    }
    __syncthreads();
#pragma unroll
    for (int i = 0; i < 8; i++) {
        int idx = threadIdx.x + (i << 8);      // 0..2047
        int kp = idx >> 7, sc = idx & 127;
        int ml;
        if (isW) {
            int ch = sc >> 5, r = sc & 31, gg = (r >> 2) & 7, nt = r & 3;
            ml = ch * 32 + nt * 8 + gg;
        } else {
            int hf = sc >> 6, r = sc & 63, hi = (r >> 5) & 1, gg = (r >> 2) & 7, mt = r & 3;
            ml = hf * 64 + mt * 16 + hi * 8 + gg;
        }
        out[(size_t)((k0 >> 1) + kp) * Rm + m0 + sc] =
            __floats2half2_rn(ts[ml][2*kp], ts[ml][2*kp+1]);
    }
}

// ---------------- GEMM fp16: 4 warps, warp tile 64x64, fp32 or fp16 out --------
#define LDH 136
#define STG_H2 (16*LDH)
#define STG_BY (STG_H2*4)     // 8704 bytes
#define GSMEM (3*2*STG_BY)    // 52224

__global__ __launch_bounds__(128, 2) void gemm_fp16(
    const __half2* __restrict__ At, const __half2* __restrict__ Wt,
    const float* __restrict__ bias, float* __restrict__ Cf, __half* __restrict__ Ch)
{
    extern __shared__ __half2 smh[];
    const uint32_t sb = smem_u32(smh);
    const int tid = threadIdx.x, wid = tid >> 5, lane = tid & 31;
    const int g = lane >> 2, tig = lane & 3;
    const int wmh = (wid >> 1) * 64;
    const int wnc = (wid & 1) * 64;
    const int bm = blockIdx.y << 7, bn = blockIdx.x << 7;

    float acc[4][8][4];
#pragma unroll
    for (int i = 0; i < 4; i++)
#pragma unroll
        for (int j = 0; j < 8; j++)
#pragma unroll
            for (int e = 0; e < 4; e++) acc[i][j][e] = 0.f;

#define LOAD_STAGE(J, S) do { \
    uint32_t dst = sb + (uint32_t)(S) * 2 * STG_BY; \
    _Pragma("unroll") \
    for (int p = 0; p < 4; p++) { \
        int ci = tid + (p << 7); \
        int row = ci >> 5, cc = ci & 31; \
        cp16(dst + row * (LDH*4) + cc * 16, \
             At + (size_t)((J) * 16 + row) * MT + bm + cc * 4); \
        cp16(dst + STG_BY + row * (LDH*4) + cc * 16, \
             Wt + (size_t)((J) * 16 + row) * DM + bn + cc * 4); \
    } \
    asm volatile("cp.async.commit_group;" ::: "memory"); \
} while (0)

    LOAD_STAGE(0, 0);
    LOAD_STAGE(1, 1);

    for (int j = 0; j < 32; j++) {
        if (j < 31) asm volatile("cp.async.wait_group 1;" ::: "memory");
        else        asm volatile("cp.async.wait_group 0;" ::: "memory");
        __syncthreads();

        const __half2* Ab = smh + (j % 3) * 2 * STG_H2;
        const __half2* Wb = Ab + STG_H2;
#pragma unroll
        for (int ks = 0; ks < 2; ks++) {
            const int kp0 = ks * 8 + tig;
            uint4 ua0 = *(const uint4*)&Ab[kp0*LDH     + wmh      + g*4];
            uint4 ua1 = *(const uint4*)&Ab[kp0*LDH     + wmh + 32 + g*4];
            uint4 ua2 = *(const uint4*)&Ab[(kp0+4)*LDH + wmh      + g*4];
            uint4 ua3 = *(const uint4*)&Ab[(kp0+4)*LDH + wmh + 32 + g*4];
            uint4 ub00 = *(const uint4*)&Wb[kp0*LDH     + wnc      + g*4];
            uint4 ub01 = *(const uint4*)&Wb[kp0*LDH     + wnc + 32 + g*4];
            uint4 ub10 = *(const uint4*)&Wb[(kp0+4)*LDH + wnc      + g*4];
            uint4 ub11 = *(const uint4*)&Wb[(kp0+4)*LDH + wnc + 32 + g*4];
            const uint32_t a0[4] = {ua0.x, ua0.y, ua0.z, ua0.w};
            const uint32_t a1[4] = {ua1.x, ua1.y, ua1.z, ua1.w};
            const uint32_t a2[4] = {ua2.x, ua2.y, ua2.z, ua2.w};
            const uint32_t a3[4] = {ua3.x, ua3.y, ua3.z, ua3.w};
            const uint32_t b0[8] = {ub00.x,ub00.y,ub00.z,ub00.w, ub01.x,ub01.y,ub01.z,ub01.w};
            const uint32_t b1[8] = {ub10.x,ub10.y,ub10.z,ub10.w, ub11.x,ub11.y,ub11.z,ub11.w};
#pragma unroll
            for (int mt = 0; mt < 4; mt++)
#pragma unroll
                for (int nt = 0; nt < 8; nt++)
                    mma16(acc[mt][nt], a0[mt], a1[mt], a2[mt], a3[mt],
                          b0[nt], b1[nt]);
        }
        if (j + 2 < 32) LOAD_STAGE(j + 2, (j + 2) % 3);
    }
#undef LOAD_STAGE

#pragma unroll
    for (int mt = 0; mt < 4; mt++) {
        int r0 = bm + (wid >> 1) * 64 + mt * 16 + g;
#pragma unroll
        for (int nt = 0; nt < 8; nt++) {
            int c = bn + (wid & 1) * 64 + (nt >> 2) * 32 + (nt & 3) * 8 + 2 * tig;
            float2 bv = *(const float2*)(bias + c);
            float o00 = acc[mt][nt][0] + bv.x, o01 = acc[mt][nt][1] + bv.y;
            float o10 = acc[mt][nt][2] + bv.x, o11 = acc[mt][nt][3] + bv.y;
            if (Ch) {
                *(uint32_t*)&Ch[(size_t)r0 * DM + c]       = packh2(o00, o01);
                *(uint32_t*)&Ch[(size_t)(r0 + 8) * DM + c] = packh2(o10, o11);
            } else {
                *(float2*)(Cf + (size_t)r0 * DM + c)       = make_float2(o00, o01);
                *(float2*)(Cf + (size_t)(r0 + 8) * DM + c) = make_float2(o10, o11);
            }
        }
    }
}

// ---------------- Flash attention v5: all-fp16 I/O ------------------------------
// O = softmax(Q K^T / 8) @ V; Oh: half row-major (+Vpost); Oat: permuted g_at.
// 256 thr, 8 warps; warp owns 16 q rows x all 64 keys. Q frags direct from gmem.
#define LDK2 72
#define ASMEM (2*32*LDK2*4)   // 18432
__global__ __launch_bounds__(256, 2) void attn_h(
    const __half* __restrict__ Q, const __half* __restrict__ Kh,
    const __half* __restrict__ V, const __half* __restrict__ Vpost,
    __half* __restrict__ Oh, __half2* __restrict__ Oat)
{
    extern __shared__ __half2 smh[];
    __half2* Ks = smh;                 // 32 dp x 72
    __half2* Vs = smh + 32*LDK2;       // 32 kp x 72

    const int tid = threadIdx.x, wid = tid >> 5, lane = tid & 31;
    const int g = lane >> 2, tig = lane & 3;
    const int wq = wid << 4;
    const int q0 = blockIdx.x << 7;
    const int bh = blockIdx.y, b = bh >> 4, h = bh & 15;
    const size_t base = (size_t)b * SS * DM + (size_t)h * DH;
    const float C = 0.125f * 1.44269504f;   // scale * log2(e), folded into exp2

    // ---- Q fragments directly from gmem (raw, unscaled) ----
    uint32_t qa[4][4];
    {
        const __half* qb = Q + base + (size_t)(q0 + wq + g) * DM;
#pragma unroll
        for (int ks = 0; ks < 4; ks++) {
            const int d0 = 2 * (ks * 8 + tig);
            qa[ks][0] = *(const uint32_t*)(qb + d0);
            qa[ks][1] = *(const uint32_t*)(qb + 8*DM + d0);
            qa[ks][2] = *(const uint32_t*)(qb + d0 + 8);
            qa[ks][3] = *(const uint32_t*)(qb + 8*DM + d0 + 8);
        }
    }

    float o[8][4];
#pragma unroll
    for (int nt = 0; nt < 8; nt++)
#pragma unroll
        for (int e = 0; e < 4; e++) o[nt][e] = 0.f;
    float m0 = -1e30f, m1 = -1e30f, l0 = 0.f, l1 = 0.f;

    const int kkey = tid & 63, kd0 = (tid >> 6) << 4;           // K loader
    const int kc = ((kkey & 7) << 3) | (kkey >> 3);
    const int vkp = tid >> 3, vdg = (tid & 7) << 3;             // V loader

    for (int kt = 0; kt < 16; kt++) {
        const int k0 = kt << 6;
        __syncthreads();

        // ---- K -> Ks[dp][k'] (no conversion, halves already d-paired) ----
        {
            const __half* kptr = Kh + base + (size_t)(k0 + kkey) * DM + kd0;
            uint4 u0 = *(const uint4*)kptr;
            uint4 u1 = *(const uint4*)(kptr + 8);
            const int dp = kd0 >> 1;
            *(uint32_t*)&Ks[(dp+0)*LDK2 + kc] = u0.x;
            *(uint32_t*)&Ks[(dp+1)*LDK2 + kc] = u0.y;
            *(uint32_t*)&Ks[(dp+2)*LDK2 + kc] = u0.z;
            *(uint32_t*)&Ks[(dp+3)*LDK2 + kc] = u0.w;
            *(uint32_t*)&Ks[(dp+4)*LDK2 + kc] = u1.x;
            *(uint32_t*)&Ks[(dp+5)*LDK2 + kc] = u1.y;
            *(uint32_t*)&Ks[(dp+6)*LDK2 + kc] = u1.z;
            *(uint32_t*)&Ks[(dp+7)*LDK2 + kc] = u1.w;
        }
        // ---- V -> Vs[keypair][d'] via PRMT row-pairing ----
        {
            const __half* v0 = V + base + (size_t)(k0 + 2*vkp) * DM + vdg;
            uint4 a = *(const uint4*)v0;
            uint4 bq = *(const uint4*)(v0 + DM);
            uint32_t* vrow = (uint32_t*)&Vs[vkp*LDK2 + (vdg >> 3)];
            vrow[0]  = prmt(a.x, bq.x, 0x5410);
            vrow[8]  = prmt(a.x, bq.x, 0x7632);
            vrow[16] = prmt(a.y, bq.y, 0x5410);
            vrow[24] = prmt(a.y, bq.y, 0x7632);
            vrow[32] = prmt(a.z, bq.z, 0x5410);
            vrow[40] = prmt(a.z, bq.z, 0x7632);
            vrow[48] = prmt(a.w, bq.w, 0x5410);
            vrow[56] = prmt(a.w, bq.w, 0x7632);
        }
        __syncthreads();

        // ---- S = Q K^T (raw scores) ----
        float s[8][4];
#pragma unroll
        for (int nt = 0; nt < 8; nt++)
#pragma unroll
            for (int e = 0; e < 4; e++) s[nt][e] = 0.f;
#pragma unroll
        for (int ks = 0; ks < 4; ks++) {
            const int dp0 = ks * 8 + tig;
            uint4 u0 = *(const uint4*)&Ks[dp0*LDK2 + g*8];
            uint4 u1 = *(const uint4*)&Ks[dp0*LDK2 + g*8 + 4];
            uint4 u2 = *(const uint4*)&Ks[(dp0+4)*LDK2 + g*8];
            uint4 u3 = *(const uint4*)&Ks[(dp0+4)*LDK2 + g*8 + 4];
            const uint32_t b0[8] = {u0.x,u0.y,u0.z,u0.w, u1.x,u1.y,u1.z,u1.w};
            const uint32_t b1[8] = {u2.x,u2.y,u2.z,u2.w, u3.x,u3.y,u3.z,u3.w};
#pragma unroll
            for (int nt = 0; nt < 8; nt++)
                mma16(s[nt], qa[ks][0], qa[ks][1], qa[ks][2], qa[ks][3],
                      b0[nt], b1[nt]);
        }

        // ---- register online softmax (scale folded into exp2) ----
        float tm0 = -1e30f, tm1 = -1e30f;
#pragma unroll
        for (int nt = 0; nt < 8; nt++) {
            tm0 = fmaxf(tm0, fmaxf(s[nt][0], s[nt][1]));
            tm1 = fmaxf(tm1, fmaxf(s[nt][2], s[nt][3]));
        }
        tm0 = fmaxf(tm0, __shfl_xor_sync(0xffffffffu, tm0, 1));
        tm0 = fmaxf(tm0, __shfl_xor_sync(0xffffffffu, tm0, 2));
        tm1 = fmaxf(tm1, __shfl_xor_sync(0xffffffffu, tm1, 1));
        tm1 = fmaxf(tm1, __shfl_xor_sync(0xffffffffu, tm1, 2));
        float mn0 = fmaxf(m0, tm0), mn1 = fmaxf(m1, tm1);
        float al0 = exp2f((m0 - mn0) * C), al1 = exp2f((m1 - mn1) * C);
        float rs0 = 0.f, rs1 = 0.f;
        uint32_t p[4][4];
#pragma unroll
        for (int ks = 0; ks < 4; ks++) {
            float e00 = exp2f((s[2*ks][0]   - mn0) * C), e01 = exp2f((s[2*ks][1]   - mn0) * C);
            float e02 = exp2f((s[2*ks][2]   - mn1) * C), e03 = exp2f((s[2*ks][3]   - mn1) * C);
            float e10 = exp2f((s[2*ks+1][0] - mn0) * C), e11 = exp2f((s[2*ks+1][1] - mn0) * C);
            float e12 = exp2f((s[2*ks+1][2] - mn1) * C), e13 = exp2f((s[2*ks+1][3] - mn1) * C);
            rs0 += (e00 + e01) + (e10 + e11);
            rs1 += (e02 + e03) + (e12 + e13);
            p[ks][0] = packh2(e00, e01);
            p[ks][1] = packh2(e02, e03);
            p[ks][2] = packh2(e10, e11);
            p[ks][3] = packh2(e12, e13);
        }
        rs0 += __shfl_xor_sync(0xffffffffu, rs0, 1);
        rs0 += __shfl_xor_sync(0xffffffffu, rs0, 2);
        rs1 += __shfl_xor_sync(0xffffffffu, rs1, 1);
        rs1 += __shfl_xor_sync(0xffffffffu, rs1, 2);
        l0 = l0 * al0 + rs0;  m0 = mn0;
        l1 = l1 * al1 + rs1;  m1 = mn1;

        // ---- rescale O, then O += P V ----
#pragma unroll
        for (int nt = 0; nt < 8; nt++) {
            o[nt][0] *= al0; o[nt][1] *= al0;
            o[nt][2] *= al1; o[nt][3] *= al1;
        }
#pragma unroll
        for (int ks = 0; ks < 4; ks++) {
            const int kp0 = ks * 8 + tig;
            uint4 u0 = *(const uint4*)&Vs[kp0*LDK2 + g*8];
            uint4 u1 = *(const uint4*)&Vs[kp0*LDK2 + g*8 + 4];
            uint4 u2 = *(const uint4*)&Vs[(kp0+4)*LDK2 + g*8];
            uint4 u3 = *(const uint4*)&Vs[(kp0+4)*LDK2 + g*8 + 4];
            const uint32_t b0[8] = {u0.x,u0.y,u0.z,u0.w, u1.x,u1.y,u1.z,u1.w};
            const uint32_t b1[8] = {u2.x,u2.y,u2.z,u2.w, u3.x,u3.y,u3.z,u3.w};
#pragma unroll
            for (int nt = 0; nt < 8; nt++)
                mma16(o[nt], p[ks][0], p[ks][1], p[ks][2], p[ks][3],
                      b0[nt], b1[nt]);
        }
    }

    // ---- normalize + store ----
    {
        float il0 = 1.f / l0, il1 = 1.f / l1;
        const int r = q0 + wq + g;
        if (Oh) {
#pragma unroll
            for (int nt = 0; nt < 8; nt++) {
                int d0 = nt * 8 + 2 * tig;
                float o00 = o[nt][0]*il0, o01 = o[nt][1]*il0;
                float o10 = o[nt][2]*il1, o11 = o[nt][3]*il1;
                if (Vpost) {
                    uint32_t v0 = *(const uint32_t*)(Vpost + base + (size_t)r * DM + d0);
                    uint32_t v1 = *(const uint32_t*)(Vpost + base + (size_t)(r+8) * DM + d0);
                    float2 f0 = __half22float2(*(__half2*)&v0);
                    float2 f1 = __half22float2(*(__half2*)&v1);
                    o00 += f0.x; o01 += f0.y; o10 += f1.x; o11 += f1.y;
                }
                *(uint32_t*)&Oh[base + (size_t)r * DM + d0]     = packh2(o00, o01);
                *(uint32_t*)&Oh[base + (size_t)(r+8) * DM + d0] = packh2(o10, o11);
            }
        } else {
            // write permuted g_at layout directly: at[kp][m], kp = h*32 + d/2
            const size_t mbase = (size_t)b * SS + q0;
            const int lq = wq + g;
            const int mp0 = ((lq >> 6) & 1) * 64 + ((lq >> 3) & 1) * 32 + (lq & 7) * 4 + ((lq >> 4) & 3);
            const int lq1 = lq + 8;
            const int mp1 = ((lq1 >> 6) & 1) * 64 + ((lq1 >> 3) & 1) * 32 + (lq1 & 7) * 4 + ((lq1 >> 4) & 3);
#pragma unroll
            for (int nt = 0; nt < 8; nt++) {
                const int kp = h * 32 + nt * 4 + tig;
                *(uint32_t*)&Oat[(size_t)kp * MT + mbase + mp0] =
                    packh2(o[nt][0]*il0, o[nt][1]*il0);
                *(uint32_t*)&Oat[(size_t)kp * MT + mbase + mp1] =
                    packh2(o[nt][2]*il1, o[nt][3]*il1);
            }
        }
    }
}

// ---------------- launch --------------------------------------------------------
extern "C" void kernel_launch(void* const* d_in, const int* in_sizes, int n_in,
                              void* d_out, int out_size) {
    (void)in_sizes; (void)n_in; (void)out_size;
    const float* gfeat = (const float*)d_in[0];
    const float* lfeat = (const float*)d_in[1];
    const float* tfeat = (const float*)d_in[2];
    const float* gqw = (const float*)d_in[3];  const float* gqb = (const float*)d_in[4];
    const float* gkw = (const float*)d_in[5];  const float* gkb = (const float*)d_in[6];
    const float* gvw = (const float*)d_in[7];  const float* gvb = (const float*)d_in[8];
    const float* pqw = (const float*)d_in[9];  const float* pqb = (const float*)d_in[10];
    const float* pkw = (const float*)d_in[11]; const float* pkb = (const float*)d_in[12];
    const float* pvw = (const float*)d_in[13]; const float* pvb = (const float*)d_in[14];
    const float* dw  = (const float*)d_in[15]; const float* db  = (const float*)d_in[16];
    float* out = (float*)d_out;

    __half *qh, *kh, *vh, *pqh, *pkh, *pvh, *a2h;
    __half2 *at, *wt;
    cudaGetSymbolAddress((void**)&qh,  g_qh);
    cudaGetSymbolAddress((void**)&kh,  g_kh);
    cudaGetSymbolAddress((void**)&vh,  g_vh);
    cudaGetSymbolAddress((void**)&pqh, g_pqh);
    cudaGetSymbolAddress((void**)&pkh, g_pkh);
    cudaGetSymbolAddress((void**)&pvh, g_pvh);
    cudaGetSymbolAddress((void**)&a2h, g_a2h);
    cudaGetSymbolAddress((void**)&at,  g_at);
    cudaGetSymbolAddress((void**)&wt,  g_wt);

    cudaFuncSetAttribute(gemm_fp16, cudaFuncAttributeMaxDynamicSharedMemorySize, GSMEM);

    dim3 gg(DM/128, MT/128);   // (8, 32)
    dim3 ga(SS/128, BB*NH);    // (8, 64)
    dim3 gca(MT/128, DM/32);   // (32, 32)
    dim3 gcw(DM/128, DM/32);   // (8, 32)

#define CONV_A(src)  conv_t<<<gca, 256>>>((src), at, MT, 0)
#define CONV_W(srcW) conv_t<<<gcw, 256>>>((srcW), wt, DM, 1)
#define GEMMH(bias, dst) gemm_fp16<<<gg, 128, GSMEM>>>(at, wt, (bias), nullptr, (dst))
#define GEMMF(bias, dst) gemm_fp16<<<gg, 128, GSMEM>>>(at, wt, (bias), (dst), nullptr)

    CONV_A(gfeat);
    CONV_W(gqw); GEMMH(gqb, qh);
    CONV_A(lfeat);
    CONV_W(gkw); GEMMH(gkb, kh);
    CONV_W(gvw); GEMMH(gvb, vh);
    CONV_W(pqw); GEMMH(pqb, pqh);
    CONV_A(tfeat);
    CONV_W(pkw); GEMMH(pkb, pkh);
    CONV_W(pvw); GEMMH(pvb, pvh);

    // att2+gv = softmax(pq pk^T/8) @ pv + gv   (half, row-major)
    attn_h<<<ga, 256, ASMEM>>>(pqh, pkh, pvh, vh, a2h, nullptr);
    // ctx = softmax(gq gk^T/8) @ (att2+gv)  -> written straight into permuted g_at
    attn_h<<<ga, 256, ASMEM>>>(qh, kh, a2h, nullptr, nullptr, at);

    CONV_W(dw); GEMMF(db, out);
#undef CONV_A
#undef CONV_W
#undef GEMMH
#undef GEMMF
}

// round 9
// speedup vs baseline: 5.8631x; 1.0597x over previous
#include <cuda_runtime.h>
#include <cuda_fp16.h>
#include <cstdint>

#define DM 1024     // d_model
#define NH 16       // heads
#define DH 64       // head dim
#define BB 4        // batch
#define SS 1024     // seq
#define MT (BB*SS)  // 4096 rows

#define ATS ((DM/2)*MT)   // half2 per activation slot
#define WTS ((DM/2)*DM)   // half2 per weight slot

// ---------------- scratch ----------------
__device__ __half2 g_acts[3*ATS];    // conv'd activations: gfeat, lfeat, tfeat
__device__ __half2 g_wts[7*WTS];     // conv'd weights: gq,gk,gv,pq,pk,pv,dense
__device__ __half  g_proj[6*(size_t)MT*DM];  // qh,kh,vh,pqh,pkh,pvh
__device__ __half  g_a2h[(size_t)MT*DM];     // att2 + gv
__device__ __half2 g_ctxat[ATS];     // ctx in permuted at-layout (attn#2 output)

struct Ptrs7 { const float* p[7]; };
struct Ptrs3 { const float* p[3]; };

__device__ __forceinline__ void mma16(float* c,
    uint32_t a0, uint32_t a1, uint32_t a2, uint32_t a3, uint32_t b0, uint32_t b1) {
    asm volatile(
        "mma.sync.aligned.m16n8k16.row.col.f32.f16.f16.f32 "
        "{%0,%1,%2,%3},{%4,%5,%6,%7},{%8,%9},{%0,%1,%2,%3};\n"
        : "+f"(c[0]), "+f"(c[1]), "+f"(c[2]), "+f"(c[3])
        : "r"(a0), "r"(a1), "r"(a2), "r"(a3), "r"(b0), "r"(b1));
}
__device__ __forceinline__ uint32_t smem_u32(const void* p) {
    uint32_t a;
    asm("{ .reg .u64 t; cvta.to.shared.u64 t, %1; cvt.u32.u64 %0, t; }" : "=r"(a) : "l"(p));
    return a;
}
__device__ __forceinline__ void cp16(uint32_t dst, const void* src) {
    asm volatile("cp.async.cg.shared.global [%0], [%1], 16;" :: "r"(dst), "l"(src) : "memory");
}
__device__ __forceinline__ uint32_t packh2(float lo, float hi) {
    uint32_t r;
    asm("cvt.rn.f16x2.f32 %0, %1, %2;" : "=r"(r) : "f"(hi), "f"(lo));
    return r;
}
__device__ __forceinline__ uint32_t prmt(uint32_t a, uint32_t b, uint32_t s) {
    uint32_t d;
    asm("prmt.b32 %0, %1, %2, %3;" : "=r"(d) : "r"(a), "r"(b), "r"(s));
    return d;
}

// ---------------- batched converts: fp32 -> half2 transposed+permuted+k-packed --
__device__ __forceinline__ void conv_body(
    const float* __restrict__ in, __half2* __restrict__ out, int Rm, int isW)
{
    __shared__ float ts[128][33];
    const int m0 = blockIdx.x << 7, k0 = blockIdx.y << 5;
#pragma unroll
    for (int i = 0; i < 4; i++) {
        int idx = threadIdx.x + (i << 8);
        int ml = idx >> 3, kc = (idx & 7) << 2;
        float4 v = *(const float4*)(in + (size_t)(m0 + ml) * 1024 + k0 + kc);
        ts[ml][kc] = v.x; ts[ml][kc+1] = v.y; ts[ml][kc+2] = v.z; ts[ml][kc+3] = v.w;
    }
    __syncthreads();
#pragma unroll
    for (int i = 0; i < 8; i++) {
        int idx = threadIdx.x + (i << 8);      // 0..2047
        int kp = idx >> 7, sc = idx & 127;
        int ml;
        if (isW) {
            int ch = sc >> 5, r = sc & 31, gg = (r >> 2) & 7, nt = r & 3;
            ml = ch * 32 + nt * 8 + gg;
        } else {
            int hf = sc >> 6, r = sc & 63, hi = (r >> 5) & 1, gg = (r >> 2) & 7, mt = r & 3;
            ml = hf * 64 + mt * 16 + hi * 8 + gg;
        }
        out[(size_t)((k0 >> 1) + kp) * Rm + m0 + sc] =
            __floats2half2_rn(ts[ml][2*kp], ts[ml][2*kp+1]);
    }
}
__global__ __launch_bounds__(256) void conv_w_all(Ptrs7 srcs, __half2* __restrict__ out) {
    conv_body(srcs.p[blockIdx.z], out + (size_t)blockIdx.z * WTS, DM, 1);
}
__global__ __launch_bounds__(256) void conv_a_all(Ptrs3 srcs, __half2* __restrict__ out) {
    conv_body(srcs.p[blockIdx.z], out + (size_t)blockIdx.z * ATS, MT, 0);
}

// ---------------- GEMM fp16: BK=64, 3-stage, 4 warps, warp tile 64x64 ----------
#define LDH 136
#define STG_H2 (32*LDH)       // 4352 half2 per operand stage
#define STG_BY (STG_H2*4)     // 17408 bytes
#define GSMEM (3*2*STG_BY)    // 104448

__global__ __launch_bounds__(128, 2) void gemm_fp16(
    const __half2* __restrict__ At, const __half2* __restrict__ Wt,
    const float* __restrict__ bias, float* __restrict__ Cf, __half* __restrict__ Ch)
{
    extern __shared__ __half2 smh[];
    const uint32_t sb = smem_u32(smh);
    const int tid = threadIdx.x, wid = tid >> 5, lane = tid & 31;
    const int g = lane >> 2, tig = lane & 3;
    const int wmh = (wid >> 1) * 64;
    const int wnc = (wid & 1) * 64;
    const int bm = blockIdx.y << 7, bn = blockIdx.x << 7;

    float acc[4][8][4];
#pragma unroll
    for (int i = 0; i < 4; i++)
#pragma unroll
        for (int j = 0; j < 8; j++)
#pragma unroll
            for (int e = 0; e < 4; e++) acc[i][j][e] = 0.f;

#define LOAD_STAGE(J, S) do { \
    uint32_t dst = sb + (uint32_t)(S) * 2 * STG_BY; \
    _Pragma("unroll") \
    for (int p = 0; p < 8; p++) { \
        int ci = tid + (p << 7); \
        int row = ci >> 5, cc = ci & 31; \
        cp16(dst + row * (LDH*4) + cc * 16, \
             At + (size_t)((J) * 32 + row) * MT + bm + cc * 4); \
        cp16(dst + STG_BY + row * (LDH*4) + cc * 16, \
             Wt + (size_t)((J) * 32 + row) * DM + bn + cc * 4); \
    } \
    asm volatile("cp.async.commit_group;" ::: "memory"); \
} while (0)

    LOAD_STAGE(0, 0);
    LOAD_STAGE(1, 1);

    for (int j = 0; j < 16; j++) {
        if (j < 15) asm volatile("cp.async.wait_group 1;" ::: "memory");
        else        asm volatile("cp.async.wait_group 0;" ::: "memory");
        __syncthreads();

        const __half2* Ab = smh + (j % 3) * 2 * STG_H2;
        const __half2* Wb = Ab + STG_H2;
#pragma unroll
        for (int ks = 0; ks < 4; ks++) {
            const int kp0 = ks * 8 + tig;
            uint4 ua0 = *(const uint4*)&Ab[kp0*LDH     + wmh      + g*4];
            uint4 ua1 = *(const uint4*)&Ab[kp0*LDH     + wmh + 32 + g*4];
            uint4 ua2 = *(const uint4*)&Ab[(kp0+4)*LDH + wmh      + g*4];
            uint4 ua3 = *(const uint4*)&Ab[(kp0+4)*LDH + wmh + 32 + g*4];
            uint4 ub00 = *(const uint4*)&Wb[kp0*LDH     + wnc      + g*4];
            uint4 ub01 = *(const uint4*)&Wb[kp0*LDH     + wnc + 32 + g*4];
            uint4 ub10 = *(const uint4*)&Wb[(kp0+4)*LDH + wnc      + g*4];
            uint4 ub11 = *(const uint4*)&Wb[(kp0+4)*LDH + wnc + 32 + g*4];
            const uint32_t a0[4] = {ua0.x, ua0.y, ua0.z, ua0.w};
            const uint32_t a1[4] = {ua1.x, ua1.y, ua1.z, ua1.w};
            const uint32_t a2[4] = {ua2.x, ua2.y, ua2.z, ua2.w};
            const uint32_t a3[4] = {ua3.x, ua3.y, ua3.z, ua3.w};
            const uint32_t b0[8] = {ub00.x,ub00.y,ub00.z,ub00.w, ub01.x,ub01.y,ub01.z,ub01.w};
            const uint32_t b1[8] = {ub10.x,ub10.y,ub10.z,ub10.w, ub11.x,ub11.y,ub11.z,ub11.w};
#pragma unroll
            for (int mt = 0; mt < 4; mt++)
#pragma unroll
                for (int nt = 0; nt < 8; nt++)
                    mma16(acc[mt][nt], a0[mt], a1[mt], a2[mt], a3[mt],
                          b0[nt], b1[nt]);
        }
        if (j + 2 < 16) LOAD_STAGE(j + 2, (j + 2) % 3);
    }
#undef LOAD_STAGE

#pragma unroll
    for (int mt = 0; mt < 4; mt++) {
        int r0 = bm + (wid >> 1) * 64 + mt * 16 + g;
#pragma unroll
        for (int nt = 0; nt < 8; nt++) {
            int c = bn + (wid & 1) * 64 + (nt >> 2) * 32 + (nt & 3) * 8 + 2 * tig;
            float2 bv = *(const float2*)(bias + c);
            float o00 = acc[mt][nt][0] + bv.x, o01 = acc[mt][nt][1] + bv.y;
            float o10 = acc[mt][nt][2] + bv.x, o11 = acc[mt][nt][3] + bv.y;
            if (Ch) {
                *(uint32_t*)&Ch[(size_t)r0 * DM + c]       = packh2(o00, o01);
                *(uint32_t*)&Ch[(size_t)(r0 + 8) * DM + c] = packh2(o10, o11);
            } else {
                *(float2*)(Cf + (size_t)r0 * DM + c)       = make_float2(o00, o01);
                *(float2*)(Cf + (size_t)(r0 + 8) * DM + c) = make_float2(o10, o11);
            }
        }
    }
}

// ---------------- Flash attention (all-fp16 I/O, unchanged from R8) -------------
#define LDK2 72
#define ASMEM (2*32*LDK2*4)   // 18432
__global__ __launch_bounds__(256, 2) void attn_h(
    const __half* __restrict__ Q, const __half* __restrict__ Kh,
    const __half* __restrict__ V, const __half* __restrict__ Vpost,
    __half* __restrict__ Oh, __half2* __restrict__ Oat)
{
    extern __shared__ __half2 smh[];
    __half2* Ks = smh;
    __half2* Vs = smh + 32*LDK2;

    const int tid = threadIdx.x, wid = tid >> 5, lane = tid & 31;
    const int g = lane >> 2, tig = lane & 3;
    const int wq = wid << 4;
    const int q0 = blockIdx.x << 7;
    const int bh = blockIdx.y, b = bh >> 4, h = bh & 15;
    const size_t base = (size_t)b * SS * DM + (size_t)h * DH;
    const float C = 0.125f * 1.44269504f;

    uint32_t qa[4][4];
    {
        const __half* qb = Q + base + (size_t)(q0 + wq + g) * DM;
#pragma unroll
        for (int ks = 0; ks < 4; ks++) {
            const int d0 = 2 * (ks * 8 + tig);
            qa[ks][0] = *(const uint32_t*)(qb + d0);
            qa[ks][1] = *(const uint32_t*)(qb + 8*DM + d0);
            qa[ks][2] = *(const uint32_t*)(qb + d0 + 8);
            qa[ks][3] = *(const uint32_t*)(qb + 8*DM + d0 + 8);
        }
    }

    float o[8][4];
#pragma unroll
    for (int nt = 0; nt < 8; nt++)
#pragma unroll
        for (int e = 0; e < 4; e++) o[nt][e] = 0.f;
    float m0 = -1e30f, m1 = -1e30f, l0 = 0.f, l1 = 0.f;

    const int kkey = tid & 63, kd0 = (tid >> 6) << 4;
    const int kc = ((kkey & 7) << 3) | (kkey >> 3);
    const int vkp = tid >> 3, vdg = (tid & 7) << 3;

    for (int kt = 0; kt < 16; kt++) {
        const int k0 = kt << 6;
        __syncthreads();

        {
            const __half* kptr = Kh + base + (size_t)(k0 + kkey) * DM + kd0;
            uint4 u0 = *(const uint4*)kptr;
            uint4 u1 = *(const uint4*)(kptr + 8);
            const int dp = kd0 >> 1;
            *(uint32_t*)&Ks[(dp+0)*LDK2 + kc] = u0.x;
            *(uint32_t*)&Ks[(dp+1)*LDK2 + kc] = u0.y;
            *(uint32_t*)&Ks[(dp+2)*LDK2 + kc] = u0.z;
            *(uint32_t*)&Ks[(dp+3)*LDK2 + kc] = u0.w;
            *(uint32_t*)&Ks[(dp+4)*LDK2 + kc] = u1.x;
            *(uint32_t*)&Ks[(dp+5)*LDK2 + kc] = u1.y;
            *(uint32_t*)&Ks[(dp+6)*LDK2 + kc] = u1.z;
            *(uint32_t*)&Ks[(dp+7)*LDK2 + kc] = u1.w;
        }
        {
            const __half* v0 = V + base + (size_t)(k0 + 2*vkp) * DM + vdg;
            uint4 a = *(const uint4*)v0;
            uint4 bq = *(const uint4*)(v0 + DM);
            uint32_t* vrow = (uint32_t*)&Vs[vkp*LDK2 + (vdg >> 3)];
            vrow[0]  = prmt(a.x, bq.x, 0x5410);
            vrow[8]  = prmt(a.x, bq.x, 0x7632);
            vrow[16] = prmt(a.y, bq.y, 0x5410);
            vrow[24] = prmt(a.y, bq.y, 0x7632);
            vrow[32] = prmt(a.z, bq.z, 0x5410);
            vrow[40] = prmt(a.z, bq.z, 0x7632);
            vrow[48] = prmt(a.w, bq.w, 0x5410);
            vrow[56] = prmt(a.w, bq.w, 0x7632);
        }
        __syncthreads();

        float s[8][4];
#pragma unroll
        for (int nt = 0; nt < 8; nt++)
#pragma unroll
            for (int e = 0; e < 4; e++) s[nt][e] = 0.f;
#pragma unroll
        for (int ks = 0; ks < 4; ks++) {
            const int dp0 = ks * 8 + tig;
            uint4 u0 = *(const uint4*)&Ks[dp0*LDK2 + g*8];
            uint4 u1 = *(const uint4*)&Ks[dp0*LDK2 + g*8 + 4];
            uint4 u2 = *(const uint4*)&Ks[(dp0+4)*LDK2 + g*8];
            uint4 u3 = *(const uint4*)&Ks[(dp0+4)*LDK2 + g*8 + 4];
            const uint32_t b0[8] = {u0.x,u0.y,u0.z,u0.w, u1.x,u1.y,u1.z,u1.w};
            const uint32_t b1[8] = {u2.x,u2.y,u2.z,u2.w, u3.x,u3.y,u3.z,u3.w};
#pragma unroll
            for (int nt = 0; nt < 8; nt++)
                mma16(s[nt], qa[ks][0], qa[ks][1], qa[ks][2], qa[ks][3],
                      b0[nt], b1[nt]);
        }

        float tm0 = -1e30f, tm1 = -1e30f;
#pragma unroll
        for (int nt = 0; nt < 8; nt++) {
            tm0 = fmaxf(tm0, fmaxf(s[nt][0], s[nt][1]));
            tm1 = fmaxf(tm1, fmaxf(s[nt][2], s[nt][3]));
        }
        tm0 = fmaxf(tm0, __shfl_xor_sync(0xffffffffu, tm0, 1));
        tm0 = fmaxf(tm0, __shfl_xor_sync(0xffffffffu, tm0, 2));
        tm1 = fmaxf(tm1, __shfl_xor_sync(0xffffffffu, tm1, 1));
        tm1 = fmaxf(tm1, __shfl_xor_sync(0xffffffffu, tm1, 2));
        float mn0 = fmaxf(m0, tm0), mn1 = fmaxf(m1, tm1);
        float al0 = exp2f((m0 - mn0) * C), al1 = exp2f((m1 - mn1) * C);
        float rs0 = 0.f, rs1 = 0.f;
        uint32_t p[4][4];
#pragma unroll
        for (int ks = 0; ks < 4; ks++) {
            float e00 = exp2f((s[2*ks][0]   - mn0) * C), e01 = exp2f((s[2*ks][1]   - mn0) * C);
            float e02 = exp2f((s[2*ks][2]   - mn1) * C), e03 = exp2f((s[2*ks][3]   - mn1) * C);
            float e10 = exp2f((s[2*ks+1][0] - mn0) * C), e11 = exp2f((s[2*ks+1][1] - mn0) * C);
            float e12 = exp2f((s[2*ks+1][2] - mn1) * C), e13 = exp2f((s[2*ks+1][3] - mn1) * C);
            rs0 += (e00 + e01) + (e10 + e11);
            rs1 += (e02 + e03) + (e12 + e13);
            p[ks][0] = packh2(e00, e01);
            p[ks][1] = packh2(e02, e03);
            p[ks][2] = packh2(e10, e11);
            p[ks][3] = packh2(e12, e13);
        }
        rs0 += __shfl_xor_sync(0xffffffffu, rs0, 1);
        rs0 += __shfl_xor_sync(0xffffffffu, rs0, 2);
        rs1 += __shfl_xor_sync(0xffffffffu, rs1, 1);
        rs1 += __shfl_xor_sync(0xffffffffu, rs1, 2);
        l0 = l0 * al0 + rs0;  m0 = mn0;
        l1 = l1 * al1 + rs1;  m1 = mn1;

#pragma unroll
        for (int nt = 0; nt < 8; nt++) {
            o[nt][0] *= al0; o[nt][1] *= al0;
            o[nt][2] *= al1; o[nt][3] *= al1;
        }
#pragma unroll
        for (int ks = 0; ks < 4; ks++) {
            const int kp0 = ks * 8 + tig;
            uint4 u0 = *(const uint4*)&Vs[kp0*LDK2 + g*8];
            uint4 u1 = *(const uint4*)&Vs[kp0*LDK2 + g*8 + 4];
            uint4 u2 = *(const uint4*)&Vs[(kp0+4)*LDK2 + g*8];
            uint4 u3 = *(const uint4*)&Vs[(kp0+4)*LDK2 + g*8 + 4];
            const uint32_t b0[8] = {u0.x,u0.y,u0.z,u0.w, u1.x,u1.y,u1.z,u1.w};
            const uint32_t b1[8] = {u2.x,u2.y,u2.z,u2.w, u3.x,u3.y,u3.z,u3.w};
#pragma unroll
            for (int nt = 0; nt < 8; nt++)
                mma16(o[nt], p[ks][0], p[ks][1], p[ks][2], p[ks][3],
                      b0[nt], b1[nt]);
        }
    }

    {
        float il0 = 1.f / l0, il1 = 1.f / l1;
        const int r = q0 + wq + g;
        if (Oh) {
#pragma unroll
            for (int nt = 0; nt < 8; nt++) {
                int d0 = nt * 8 + 2 * tig;
                float o00 = o[nt][0]*il0, o01 = o[nt][1]*il0;
                float o10 = o[nt][2]*il1, o11 = o[nt][3]*il1;
                if (Vpost) {
                    uint32_t v0 = *(const uint32_t*)(Vpost + base + (size_t)r * DM + d0);
                    uint32_t v1 = *(const uint32_t*)(Vpost + base + (size_t)(r+8) * DM + d0);
                    float2 f0 = __half22float2(*(__half2*)&v0);
                    float2 f1 = __half22float2(*(__half2*)&v1);
                    o00 += f0.x; o01 += f0.y; o10 += f1.x; o11 += f1.y;
                }
                *(uint32_t*)&Oh[base + (size_t)r * DM + d0]     = packh2(o00, o01);
                *(uint32_t*)&Oh[base + (size_t)(r+8) * DM + d0] = packh2(o10, o11);
            }
        } else {
            const size_t mbase = (size_t)b * SS + q0;
            const int lq = wq + g;
            const int mp0 = ((lq >> 6) & 1) * 64 + ((lq >> 3) & 1) * 32 + (lq & 7) * 4 + ((lq >> 4) & 3);
            const int lq1 = lq + 8;
            const int mp1 = ((lq1 >> 6) & 1) * 64 + ((lq1 >> 3) & 1) * 32 + (lq1 & 7) * 4 + ((lq1 >> 4) & 3);
#pragma unroll
            for (int nt = 0; nt < 8; nt++) {
                const int kp = h * 32 + nt * 4 + tig;
                *(uint32_t*)&Oat[(size_t)kp * MT + mbase + mp0] =
                    packh2(o[nt][0]*il0, o[nt][1]*il0);
                *(uint32_t*)&Oat[(size_t)kp * MT + mbase + mp1] =
                    packh2(o[nt][2]*il1, o[nt][3]*il1);
            }
        }
    }
}

// ---------------- launch --------------------------------------------------------
extern "C" void kernel_launch(void* const* d_in, const int* in_sizes, int n_in,
                              void* d_out, int out_size) {
    (void)in_sizes; (void)n_in; (void)out_size;
    const float* gfeat = (const float*)d_in[0];
    const float* lfeat = (const float*)d_in[1];
    const float* tfeat = (const float*)d_in[2];
    const float* gqw = (const float*)d_in[3];  const float* gqb = (const float*)d_in[4];
    const float* gkw = (const float*)d_in[5];  const float* gkb = (const float*)d_in[6];
    const float* gvw = (const float*)d_in[7];  const float* gvb = (const float*)d_in[8];
    const float* pqw = (const float*)d_in[9];  const float* pqb = (const float*)d_in[10];
    const float* pkw = (const float*)d_in[11]; const float* pkb = (const float*)d_in[12];
    const float* pvw = (const float*)d_in[13]; const float* pvb = (const float*)d_in[14];
    const float* dw  = (const float*)d_in[15]; const float* db  = (const float*)d_in[16];
    float* out = (float*)d_out;

    __half2 *acts, *wts, *ctxat;
    __half *proj, *a2h;
    cudaGetSymbolAddress((void**)&acts,  g_acts);
    cudaGetSymbolAddress((void**)&wts,   g_wts);
    cudaGetSymbolAddress((void**)&proj,  g_proj);
    cudaGetSymbolAddress((void**)&a2h,   g_a2h);
    cudaGetSymbolAddress((void**)&ctxat, g_ctxat);

    __half* qh  = proj;
    __half* kh  = proj + 1*(size_t)MT*DM;
    __half* vh  = proj + 2*(size_t)MT*DM;
    __half* pqh = proj + 3*(size_t)MT*DM;
    __half* pkh = proj + 4*(size_t)MT*DM;
    __half* pvh = proj + 5*(size_t)MT*DM;

    cudaFuncSetAttribute(gemm_fp16, cudaFuncAttributeMaxDynamicSharedMemorySize, GSMEM);

    dim3 gg(DM/128, MT/128);          // (8, 32)
    dim3 ga(SS/128, BB*NH);           // (8, 64)
    dim3 gcw(DM/128, DM/32, 7);       // all weights
    dim3 gca(MT/128, DM/32, 3);       // all activations

    Ptrs7 wp = {{ gqw, gkw, gvw, pqw, pkw, pvw, dw }};
    Ptrs3 ap = {{ gfeat, lfeat, tfeat }};
    conv_w_all<<<gcw, 256>>>(wp, wts);
    conv_a_all<<<gca, 256>>>(ap, acts);

    const __half2* atG = acts;
    const __half2* atL = acts + ATS;
    const __half2* atT = acts + 2*ATS;

#define GEMMH(A, wi, bias, dst) gemm_fp16<<<gg, 128, GSMEM>>>((A), wts + (wi)*(size_t)WTS, (bias), nullptr, (dst))
    GEMMH(atG, 0, gqb, qh);
    GEMMH(atL, 1, gkb, kh);
    GEMMH(atL, 2, gvb, vh);
    GEMMH(atL, 3, pqb, pqh);
    GEMMH(atT, 4, pkb, pkh);
    GEMMH(atT, 5, pvb, pvh);
#undef GEMMH

    // att2+gv = softmax(pq pk^T/8) @ pv + gv
    attn_h<<<ga, 256, ASMEM>>>(pqh, pkh, pvh, vh, a2h, nullptr);
    // ctx = softmax(gq gk^T/8) @ (att2+gv) -> permuted at-layout
    attn_h<<<ga, 256, ASMEM>>>(qh, kh, a2h, nullptr, nullptr, ctxat);

    // dense: fp32 out
    gemm_fp16<<<gg, 128, GSMEM>>>(ctxat, wts + 6*(size_t)WTS, db, out, nullptr);
}